// round 1
// baseline (speedup 1.0000x reference)
#include <cuda_runtime.h>
#include <cuda_bf16.h>
#include <math.h>

// Problem constants
#define LSEQ 4096
#define DMODEL 1024
#define NHEAD 16
#define NAR 8
#define DHEAD 64
#define NKT (LSEQ / 64)   // 64 key tiles of 64

// Scratch (allocation-free rule: __device__ globals)
__device__ float g_Q[LSEQ * DMODEL];
__device__ float g_K[LSEQ * DMODEL];
__device__ float g_V[LSEQ * DMODEL];
__device__ float g_O[LSEQ * DMODEL];

// ---------------------------------------------------------------------------
// SGEMM: C[4096,1024] = A[4096,1024] @ B[1024,1024], all row-major fp32.
// 128x128 tile, BK=8, 256 threads, 8x8 per thread, prefetched global loads.
// ---------------------------------------------------------------------------
__global__ void __launch_bounds__(256) sgemm128(const float* __restrict__ A,
                                                const float* __restrict__ B,
                                                float* __restrict__ C) {
    __shared__ float Ast[8][128];  // [k][m] (A transposed in smem)
    __shared__ float Bs[8][128];   // [k][n]

    const int tid = threadIdx.x;
    const int ty = tid >> 4;          // 0..15 -> rows ty*8..ty*8+7
    const int tx = tid & 15;          // 0..15 -> cols tx*8..tx*8+7
    const int brow = blockIdx.y << 7;
    const int bcol = blockIdx.x << 7;

    // A tile load mapping: 128 rows x 8 cols = 256 float4
    const int ar = tid >> 1;            // 0..127
    const int ac = (tid & 1) << 2;      // 0 or 4
    // B tile load mapping: 8 rows x 128 cols = 256 float4
    const int br = tid >> 5;            // 0..7
    const int bc = (tid & 31) << 2;     // 0..124

    const float* Aptr = A + (brow + ar) * DMODEL + ac;
    const float* Bptr = B + br * DMODEL + bcol + bc;

    float4 a4 = *reinterpret_cast<const float4*>(Aptr);
    float4 b4 = *reinterpret_cast<const float4*>(Bptr);

    float acc[8][8];
#pragma unroll
    for (int i = 0; i < 8; i++)
#pragma unroll
        for (int j = 0; j < 8; j++) acc[i][j] = 0.0f;

    for (int k0 = 0; k0 < DMODEL; k0 += 8) {
        // store current tiles
        Ast[ac + 0][ar] = a4.x;
        Ast[ac + 1][ar] = a4.y;
        Ast[ac + 2][ar] = a4.z;
        Ast[ac + 3][ar] = a4.w;
        *reinterpret_cast<float4*>(&Bs[br][bc]) = b4;
        __syncthreads();

        // prefetch next tiles (overlaps with compute below)
        if (k0 + 8 < DMODEL) {
            a4 = *reinterpret_cast<const float4*>(Aptr + k0 + 8);
            b4 = *reinterpret_cast<const float4*>(Bptr + (k0 + 8) * DMODEL);
        }

#pragma unroll
        for (int kk = 0; kk < 8; kk++) {
            float4 a0 = *reinterpret_cast<const float4*>(&Ast[kk][ty * 8]);
            float4 a1 = *reinterpret_cast<const float4*>(&Ast[kk][ty * 8 + 4]);
            float4 b0 = *reinterpret_cast<const float4*>(&Bs[kk][tx * 8]);
            float4 b1 = *reinterpret_cast<const float4*>(&Bs[kk][tx * 8 + 4]);
            float av[8] = {a0.x, a0.y, a0.z, a0.w, a1.x, a1.y, a1.z, a1.w};
            float bv[8] = {b0.x, b0.y, b0.z, b0.w, b1.x, b1.y, b1.z, b1.w};
#pragma unroll
            for (int i = 0; i < 8; i++)
#pragma unroll
                for (int j = 0; j < 8; j++)
                    acc[i][j] = fmaf(av[i], bv[j], acc[i][j]);
        }
        __syncthreads();
    }

#pragma unroll
    for (int i = 0; i < 8; i++) {
        float* Crow = C + (brow + ty * 8 + i) * DMODEL + bcol + tx * 8;
        *reinterpret_cast<float4*>(Crow) =
            make_float4(acc[i][0], acc[i][1], acc[i][2], acc[i][3]);
        *reinterpret_cast<float4*>(Crow + 4) =
            make_float4(acc[i][4], acc[i][5], acc[i][6], acc[i][7]);
    }
}

// ---------------------------------------------------------------------------
// RoPE in-place on Q and K. One thread per (row, head, freq-pair).
// Angle product computed in fp32 (matches jax), trig in fp64 (accurate for
// args up to 4096 rad, where fast fp32 trig would break).
// ---------------------------------------------------------------------------
__global__ void __launch_bounds__(512) rope_kernel(float* __restrict__ Q,
                                                   float* __restrict__ K) {
    int idx = blockIdx.x * 512 + threadIdx.x;  // 4096 * 512 total
    int row = idx >> 9;
    int rem = idx & 511;
    int h = rem >> 5;
    int jj = rem & 31;

    float invf = (float)pow(10000.0, -(double)jj / 32.0);
    float ang = (float)row * invf;  // fp32 product like jax
    double sd, cd;
    sincos((double)ang, &sd, &cd);
    float cs = (float)cd, sn = (float)sd;

    int base = row * DMODEL + h * DHEAD;

    float q1 = Q[base + jj], q2 = Q[base + jj + 32];
    Q[base + jj]      = fmaf(q1, cs, -q2 * sn);
    Q[base + jj + 32] = fmaf(q2, cs,  q1 * sn);

    float k1 = K[base + jj], k2 = K[base + jj + 32];
    K[base + jj]      = fmaf(k1, cs, -k2 * sn);
    K[base + jj + 32] = fmaf(k2, cs,  k1 * sn);
}

// ---------------------------------------------------------------------------
// Flash attention, fp32. grid = (64 q-tiles, 16 heads), 256 threads.
// Heads 0..7 causal, 8..15 full. 64x64 tiles, online softmax.
// smem = Qs(T) + KP (K(T) reused as P(T)) + Vs = 48KB exactly.
// ---------------------------------------------------------------------------
__global__ void __launch_bounds__(256) flash_kernel(const float* __restrict__ Q,
                                                    const float* __restrict__ K,
                                                    const float* __restrict__ V,
                                                    float* __restrict__ O) {
    __shared__ float Qs[64][64];  // [d][q]
    __shared__ float KP[64][64];  // [d][k] for K, then [k][q] for P
    __shared__ float Vs[64][64];  // [k][d]

    const int tid = threadIdx.x;
    const int ty = tid >> 4;  // 0..15 -> q rows ty*4..+3
    const int tx = tid & 15;  // 0..15 -> k cols / d cols tx*4..+3
    const int qt = blockIdx.x;
    const int h = blockIdx.y;
    const bool causal = (h < NAR);
    const float scale = 0.125f;  // 1/sqrt(64)

    // Load Q tile transposed into smem: Qs[d][q]
#pragma unroll
    for (int t = 0; t < 4; t++) {
        int s = tid + t * 256;
        int r = s >> 4;              // 0..63 (query within tile)
        int c = (s & 15) << 2;       // 0..60 (dim)
        float4 v4 = *reinterpret_cast<const float4*>(
            &Q[(qt * 64 + r) * DMODEL + h * DHEAD + c]);
        Qs[c + 0][r] = v4.x;
        Qs[c + 1][r] = v4.y;
        Qs[c + 2][r] = v4.z;
        Qs[c + 3][r] = v4.w;
    }

    float acc[4][4];
    float m_i[4], l_i[4];
#pragma unroll
    for (int i = 0; i < 4; i++) {
        m_i[i] = -1e30f;
        l_i[i] = 0.0f;
#pragma unroll
        for (int j = 0; j < 4; j++) acc[i][j] = 0.0f;
    }

    const int ktiles = causal ? (qt + 1) : NKT;

    for (int kt = 0; kt < ktiles; kt++) {
        __syncthreads();  // prior-iter smem reads done; Qs stores visible (iter 0)

        // Load K tile transposed (KP[d][k]) and V tile (Vs[k][d])
#pragma unroll
        for (int t = 0; t < 4; t++) {
            int s = tid + t * 256;
            int r = s >> 4;
            int c = (s & 15) << 2;
            float4 kv = *reinterpret_cast<const float4*>(
                &K[(kt * 64 + r) * DMODEL + h * DHEAD + c]);
            KP[c + 0][r] = kv.x;
            KP[c + 1][r] = kv.y;
            KP[c + 2][r] = kv.z;
            KP[c + 3][r] = kv.w;
            float4 vv = *reinterpret_cast<const float4*>(
                &V[(kt * 64 + r) * DMODEL + h * DHEAD + c]);
            *reinterpret_cast<float4*>(&Vs[r][c]) = vv;
        }
        __syncthreads();

        // S = (Q K^T) * scale
        float sv[4][4];
#pragma unroll
        for (int i = 0; i < 4; i++)
#pragma unroll
            for (int j = 0; j < 4; j++) sv[i][j] = 0.0f;

#pragma unroll
        for (int d = 0; d < 64; d++) {
            float4 qa = *reinterpret_cast<const float4*>(&Qs[d][ty * 4]);
            float4 kb = *reinterpret_cast<const float4*>(&KP[d][tx * 4]);
            float qv[4] = {qa.x, qa.y, qa.z, qa.w};
            float kv[4] = {kb.x, kb.y, kb.z, kb.w};
#pragma unroll
            for (int i = 0; i < 4; i++)
#pragma unroll
                for (int j = 0; j < 4; j++)
                    sv[i][j] = fmaf(qv[i], kv[j], sv[i][j]);
        }

#pragma unroll
        for (int i = 0; i < 4; i++)
#pragma unroll
            for (int j = 0; j < 4; j++) sv[i][j] *= scale;

        if (causal && kt == qt) {
#pragma unroll
            for (int i = 0; i < 4; i++)
#pragma unroll
                for (int j = 0; j < 4; j++)
                    if (tx * 4 + j > ty * 4 + i) sv[i][j] = -1e30f;
        }

        // Row max across own 4 cols then across 16 tx lanes
        float mnew[4];
#pragma unroll
        for (int i = 0; i < 4; i++) {
            mnew[i] = fmaxf(fmaxf(sv[i][0], sv[i][1]), fmaxf(sv[i][2], sv[i][3]));
        }
#pragma unroll
        for (int off = 8; off >= 1; off >>= 1) {
#pragma unroll
            for (int i = 0; i < 4; i++)
                mnew[i] = fmaxf(mnew[i], __shfl_xor_sync(0xffffffffu, mnew[i], off));
        }

        float alpha[4], rsum[4];
#pragma unroll
        for (int i = 0; i < 4; i++) {
            float mt = fmaxf(m_i[i], mnew[i]);
            alpha[i] = __expf(m_i[i] - mt);
            m_i[i] = mt;
            rsum[i] = 0.0f;
#pragma unroll
            for (int j = 0; j < 4; j++) {
                float p = __expf(sv[i][j] - mt);
                sv[i][j] = p;
                rsum[i] += p;
            }
        }
#pragma unroll
        for (int off = 8; off >= 1; off >>= 1) {
#pragma unroll
            for (int i = 0; i < 4; i++)
                rsum[i] += __shfl_xor_sync(0xffffffffu, rsum[i], off);
        }
#pragma unroll
        for (int i = 0; i < 4; i++) {
            l_i[i] = l_i[i] * alpha[i] + rsum[i];
#pragma unroll
            for (int j = 0; j < 4; j++) acc[i][j] *= alpha[i];
        }

        __syncthreads();  // done reading KP as K

        // Store P transposed: KP[k][q]
#pragma unroll
        for (int j = 0; j < 4; j++) {
            *reinterpret_cast<float4*>(&KP[tx * 4 + j][ty * 4]) =
                make_float4(sv[0][j], sv[1][j], sv[2][j], sv[3][j]);
        }
        __syncthreads();

        // acc += P @ V
#pragma unroll
        for (int k = 0; k < 64; k++) {
            float4 pa = *reinterpret_cast<const float4*>(&KP[k][ty * 4]);
            float4 vb = *reinterpret_cast<const float4*>(&Vs[k][tx * 4]);
            float pv[4] = {pa.x, pa.y, pa.z, pa.w};
            float vv[4] = {vb.x, vb.y, vb.z, vb.w};
#pragma unroll
            for (int i = 0; i < 4; i++)
#pragma unroll
                for (int j = 0; j < 4; j++)
                    acc[i][j] = fmaf(pv[i], vv[j], acc[i][j]);
        }
    }

    // Epilogue: normalize and write O[q][h*64+d]
#pragma unroll
    for (int i = 0; i < 4; i++) {
        float inv = 1.0f / l_i[i];
        float* Orow = O + (qt * 64 + ty * 4 + i) * DMODEL + h * DHEAD + tx * 4;
        *reinterpret_cast<float4*>(Orow) = make_float4(
            acc[i][0] * inv, acc[i][1] * inv, acc[i][2] * inv, acc[i][3] * inv);
    }
}

// ---------------------------------------------------------------------------
// Launch
// ---------------------------------------------------------------------------
extern "C" void kernel_launch(void* const* d_in, const int* in_sizes, int n_in,
                              void* d_out, int out_size) {
    const float* X  = (const float*)d_in[0];
    const float* Wq = (const float*)d_in[1];
    const float* Wk = (const float*)d_in[2];
    const float* Wv = (const float*)d_in[3];
    const float* Wo = (const float*)d_in[4];
    float* out = (float*)d_out;

    float *Qp, *Kp, *Vp, *Op;
    cudaGetSymbolAddress((void**)&Qp, g_Q);
    cudaGetSymbolAddress((void**)&Kp, g_K);
    cudaGetSymbolAddress((void**)&Vp, g_V);
    cudaGetSymbolAddress((void**)&Op, g_O);

    dim3 gemm_grid(DMODEL / 128, LSEQ / 128);  // (8, 32)
    sgemm128<<<gemm_grid, 256>>>(X, Wq, Qp);
    sgemm128<<<gemm_grid, 256>>>(X, Wk, Kp);
    sgemm128<<<gemm_grid, 256>>>(X, Wv, Vp);

    rope_kernel<<<LSEQ, 512>>>(Qp, Kp);  // 4096 blocks x 512 = (row, h, jj)

    dim3 attn_grid(LSEQ / 64, NHEAD);  // (64, 16)
    flash_kernel<<<attn_grid, 256>>>(Qp, Kp, Vp, Op);

    sgemm128<<<gemm_grid, 256>>>(Op, Wo, out);
}

// round 4
// speedup vs baseline: 1.3652x; 1.3652x over previous
#include <cuda_runtime.h>
#include <cuda_bf16.h>
#include <math.h>
#include <stdint.h>

// Problem constants
#define LSEQ 4096
#define DMODEL 1024
#define NHEAD 16
#define NAR 8
#define DHEAD 64
#define NKT (LSEQ / 64)
#define NCHUNK (DMODEL / 32)   // 32 K-chunks of 32

// ---------------------------------------------------------------------------
// Scratch (__device__ globals; no allocation allowed)
// ---------------------------------------------------------------------------
__device__ float g_Q[LSEQ * DMODEL];
__device__ float g_K[LSEQ * DMODEL];
__device__ float g_V[LSEQ * DMODEL];
__device__ float g_O[LSEQ * DMODEL];
__device__ __nv_bfloat16 g_Ah[LSEQ * DMODEL];    // split of A operand (X, then O)
__device__ __nv_bfloat16 g_Al[LSEQ * DMODEL];
__device__ __nv_bfloat16 g_Bth[DMODEL * DMODEL]; // transposed split weight [N,K]
__device__ __nv_bfloat16 g_Btl[DMODEL * DMODEL];
__device__ float2 g_rope[LSEQ * 32];             // cos/sin table

// ---------------------------------------------------------------------------
// PTX helpers (base sm_103-safe: mma.sync / ldmatrix / cp.async only)
// ---------------------------------------------------------------------------
__device__ __forceinline__ uint32_t smem_u32(const void* p) {
    uint32_t a;
    asm("{ .reg .u64 t; cvta.to.shared.u64 t, %1; cvt.u32.u64 %0, t; }"
        : "=r"(a) : "l"(p));
    return a;
}

#define CP16(dst, src) \
    asm volatile("cp.async.cg.shared.global [%0], [%1], 16;" \
                 :: "r"(dst), "l"(src) : "memory")
#define CP_COMMIT() asm volatile("cp.async.commit_group;" ::: "memory")

__device__ __forceinline__ void ldsm4(uint32_t* r, uint32_t addr) {
    asm volatile("ldmatrix.sync.aligned.m8n8.x4.shared.b16 {%0,%1,%2,%3}, [%4];"
                 : "=r"(r[0]), "=r"(r[1]), "=r"(r[2]), "=r"(r[3]) : "r"(addr));
}

#define MMA16816(d, a, b)                                                       \
    asm volatile(                                                               \
        "mma.sync.aligned.m16n8k16.row.col.f32.bf16.bf16.f32 "                  \
        "{%0,%1,%2,%3}, {%4,%5,%6,%7}, {%8,%9}, {%0,%1,%2,%3};"                 \
        : "+f"((d)[0]), "+f"((d)[1]), "+f"((d)[2]), "+f"((d)[3])                \
        : "r"((a)[0]), "r"((a)[1]), "r"((a)[2]), "r"((a)[3]),                   \
          "r"((b)[0]), "r"((b)[1]))

// Swizzled smem offset: 128 rows x 32 bf16 (64B/row), 16B chunks 0..3.
// chunk' = chunk ^ ((row>>1)&3)  -> ldmatrix 8-lane phases are conflict-free.
__device__ __forceinline__ uint32_t swz(int row, int chunk) {
    return (uint32_t)(row * 64 + ((chunk ^ ((row >> 1) & 3)) << 4));
}

// ---------------------------------------------------------------------------
// Split kernel: fp32 -> (bf16 hi, bf16 lo)
// ---------------------------------------------------------------------------
__global__ void __launch_bounds__(256) split_kernel(const float* __restrict__ src,
                                                    __nv_bfloat16* __restrict__ hi,
                                                    __nv_bfloat16* __restrict__ lo) {
    int idx = blockIdx.x * 256 + threadIdx.x;  // over float4s
    float4 v = reinterpret_cast<const float4*>(src)[idx];
    float x[4] = {v.x, v.y, v.z, v.w};
    __nv_bfloat16 h[4], l[4];
#pragma unroll
    for (int i = 0; i < 4; i++) {
        h[i] = __float2bfloat16(x[i]);
        l[i] = __float2bfloat16(x[i] - __bfloat162float(h[i]));
    }
    reinterpret_cast<__nv_bfloat162*>(hi)[idx * 2 + 0] = __nv_bfloat162(h[0], h[1]);
    reinterpret_cast<__nv_bfloat162*>(hi)[idx * 2 + 1] = __nv_bfloat162(h[2], h[3]);
    reinterpret_cast<__nv_bfloat162*>(lo)[idx * 2 + 0] = __nv_bfloat162(l[0], l[1]);
    reinterpret_cast<__nv_bfloat162*>(lo)[idx * 2 + 1] = __nv_bfloat162(l[2], l[3]);
}

// ---------------------------------------------------------------------------
// Transpose+split: W[K,N] fp32 -> Bt_hi/Bt_lo [N,K] bf16
// ---------------------------------------------------------------------------
__global__ void __launch_bounds__(256) wsplit_t_kernel(const float* __restrict__ W,
                                                       __nv_bfloat16* __restrict__ bth,
                                                       __nv_bfloat16* __restrict__ btl) {
    __shared__ float s[32][33];
    int tx = threadIdx.x & 31, ty = threadIdx.x >> 5;
    int n0 = blockIdx.x * 32, k0 = blockIdx.y * 32;
#pragma unroll
    for (int j = 0; j < 4; j++)
        s[ty + j * 8][tx] = W[(k0 + ty + j * 8) * DMODEL + n0 + tx];
    __syncthreads();
#pragma unroll
    for (int j = 0; j < 4; j++) {
        float x = s[tx][ty + j * 8];
        __nv_bfloat16 h = __float2bfloat16(x);
        __nv_bfloat16 l = __float2bfloat16(x - __bfloat162float(h));
        int o = (n0 + ty + j * 8) * DMODEL + k0 + tx;
        bth[o] = h;
        btl[o] = l;
    }
}

// ---------------------------------------------------------------------------
// HMMA GEMM: C[4096,1024] = A @ B^T with 3-term bf16 split, fp32 accum.
// A: (Ah, Al) [M,K] row-major bf16.  B: (Bh, Bl) [N,K] row-major bf16.
// CTA 128x128, BK=32, 8 warps (4M x 2N), warp tile 32x64.
// cp.async double-buffered smem: 2 stages x (4 arrays x 8KB) = 64KB.
// ---------------------------------------------------------------------------
#define GEMM_SMEM 65536

__global__ void __launch_bounds__(256) gemm_mma(const __nv_bfloat16* __restrict__ Ah,
                                                const __nv_bfloat16* __restrict__ Al,
                                                const __nv_bfloat16* __restrict__ Bh,
                                                const __nv_bfloat16* __restrict__ Bl,
                                                float* __restrict__ C) {
    extern __shared__ char sm[];
    const uint32_t sb = smem_u32(sm);
    const int tid = threadIdx.x;
    const int wid = tid >> 5, lane = tid & 31;
    const int m0 = blockIdx.y << 7;
    const int n0 = blockIdx.x << 7;
    const int wm = (wid & 3) * 32;   // warp M offset in tile
    const int wn = (wid >> 2) * 64;  // warp N offset in tile

    // copy mapping: row cr = tid>>1, two 16B chunks per thread per array
    const int cr = tid >> 1;
    const int cbase = (tid & 1) << 1;

    float acc[2][8][4];
#pragma unroll
    for (int a = 0; a < 2; a++)
#pragma unroll
        for (int n = 0; n < 8; n++)
#pragma unroll
            for (int j = 0; j < 4; j++) acc[a][n][j] = 0.0f;

#define ISSUE(chunk, buf)                                                        \
    do {                                                                         \
        const int _k0 = (chunk) * 32;                                            \
        const uint32_t _sbb = sb + (buf) * 32768u;                               \
        _Pragma("unroll")                                                        \
        for (int _j = 0; _j < 2; _j++) {                                         \
            const int _cc = cbase + _j;                                          \
            const uint32_t _so = swz(cr, _cc);                                   \
            const size_t _ea = (size_t)(m0 + cr) * DMODEL + _k0 + _cc * 8;       \
            const size_t _eb = (size_t)(n0 + cr) * DMODEL + _k0 + _cc * 8;       \
            CP16(_sbb + _so,          (const void*)(Ah + _ea));                  \
            CP16(_sbb + 8192u + _so,  (const void*)(Al + _ea));                  \
            CP16(_sbb + 16384u + _so, (const void*)(Bh + _eb));                  \
            CP16(_sbb + 24576u + _so, (const void*)(Bl + _eb));                  \
        }                                                                        \
    } while (0)

    ISSUE(0, 0);
    CP_COMMIT();
    ISSUE(1, 1);
    CP_COMMIT();

#pragma unroll 1
    for (int c = 0; c < NCHUNK; c++) {
        if (c < NCHUNK - 1)
            asm volatile("cp.async.wait_group 1;" ::: "memory");
        else
            asm volatile("cp.async.wait_group 0;" ::: "memory");
        __syncthreads();

        const uint32_t ab = sb + (c & 1) * 32768u;          // Ah base
        const uint32_t bbb = ab + 16384u;                   // Bh base

#pragma unroll
        for (int ks = 0; ks < 2; ks++) {
            uint32_t ah[2][4], al[2][4];
#pragma unroll
            for (int a = 0; a < 2; a++) {
                const int row = wm + a * 16 + ((lane >> 3) & 1) * 8 + (lane & 7);
                const int ch = ks * 2 + (lane >> 4);
                const uint32_t off = swz(row, ch);
                ldsm4(ah[a], ab + off);
                ldsm4(al[a], ab + 8192u + off);
            }
#pragma unroll
            for (int g = 0; g < 4; g++) {
                const int row = wn + g * 16 + ((lane >> 4) & 1) * 8 + (lane & 7);
                const int ch = ks * 2 + ((lane >> 3) & 1);
                const uint32_t off = swz(row, ch);
                uint32_t bh[4], bl[4];
                ldsm4(bh, bbb + off);
#pragma unroll
                for (int a = 0; a < 2; a++) {
                    MMA16816(acc[a][2 * g + 0], ah[a], bh + 0);
                    MMA16816(acc[a][2 * g + 1], ah[a], bh + 2);
                    MMA16816(acc[a][2 * g + 0], al[a], bh + 0);
                    MMA16816(acc[a][2 * g + 1], al[a], bh + 2);
                }
                ldsm4(bl, bbb + 8192u + off);
#pragma unroll
                for (int a = 0; a < 2; a++) {
                    MMA16816(acc[a][2 * g + 0], ah[a], bl + 0);
                    MMA16816(acc[a][2 * g + 1], ah[a], bl + 2);
                }
            }
        }
        __syncthreads();

        if (c + 2 < NCHUNK) {
            ISSUE(c + 2, c & 1);
            CP_COMMIT();
        }
    }
#undef ISSUE

    // Epilogue: lane l holds rows (l>>2, l>>2+8), cols (l&3)*2..+1 per atom
    const int er = lane >> 2;
    const int ec = (lane & 3) * 2;
#pragma unroll
    for (int a = 0; a < 2; a++) {
#pragma unroll
        for (int n = 0; n < 8; n++) {
            float* p0 = C + (size_t)(m0 + wm + a * 16 + er) * DMODEL + n0 + wn + n * 8 + ec;
            float* p1 = p0 + 8 * DMODEL;
            *reinterpret_cast<float2*>(p0) = make_float2(acc[a][n][0], acc[a][n][1]);
            *reinterpret_cast<float2*>(p1) = make_float2(acc[a][n][2], acc[a][n][3]);
        }
    }
}

// ---------------------------------------------------------------------------
// RoPE: table precompute + apply
// ---------------------------------------------------------------------------
__global__ void __launch_bounds__(256) rope_table_kernel(float2* __restrict__ tab) {
    int idx = blockIdx.x * 256 + threadIdx.x;  // 131072
    int row = idx >> 5, jj = idx & 31;
    float invf = (float)pow(10000.0, -(double)jj / 32.0);
    float ang = (float)row * invf;  // fp32 product like jax
    double s, c;
    sincos((double)ang, &s, &c);
    tab[idx] = make_float2((float)c, (float)s);
}

__global__ void __launch_bounds__(512) rope_apply_kernel(float* __restrict__ Q,
                                                         float* __restrict__ K,
                                                         const float2* __restrict__ tab) {
    int idx = blockIdx.x * 512 + threadIdx.x;
    int row = idx >> 9;
    int rem = idx & 511;
    int h = rem >> 5;
    int jj = rem & 31;

    float2 cs2 = tab[(row << 5) | jj];
    float cs = cs2.x, sn = cs2.y;
    int base = row * DMODEL + h * DHEAD;

    float q1 = Q[base + jj], q2 = Q[base + jj + 32];
    Q[base + jj]      = fmaf(q1, cs, -q2 * sn);
    Q[base + jj + 32] = fmaf(q2, cs,  q1 * sn);

    float k1 = K[base + jj], k2 = K[base + jj + 32];
    K[base + jj]      = fmaf(k1, cs, -k2 * sn);
    K[base + jj + 32] = fmaf(k2, cs,  k1 * sn);
}

// ---------------------------------------------------------------------------
// Flash attention, fp32 (unchanged). grid=(64 q-tiles, 16 heads), 256 thr.
// ---------------------------------------------------------------------------
__global__ void __launch_bounds__(256) flash_kernel(const float* __restrict__ Q,
                                                    const float* __restrict__ K,
                                                    const float* __restrict__ V,
                                                    float* __restrict__ O) {
    __shared__ float Qs[64][64];
    __shared__ float KP[64][64];
    __shared__ float Vs[64][64];

    const int tid = threadIdx.x;
    const int ty = tid >> 4;
    const int tx = tid & 15;
    const int qt = blockIdx.x;
    const int h = blockIdx.y;
    const bool causal = (h < NAR);
    const float scale = 0.125f;

#pragma unroll
    for (int t = 0; t < 4; t++) {
        int s = tid + t * 256;
        int r = s >> 4;
        int c = (s & 15) << 2;
        float4 v4 = *reinterpret_cast<const float4*>(
            &Q[(qt * 64 + r) * DMODEL + h * DHEAD + c]);
        Qs[c + 0][r] = v4.x;
        Qs[c + 1][r] = v4.y;
        Qs[c + 2][r] = v4.z;
        Qs[c + 3][r] = v4.w;
    }

    float acc[4][4];
    float m_i[4], l_i[4];
#pragma unroll
    for (int i = 0; i < 4; i++) {
        m_i[i] = -1e30f;
        l_i[i] = 0.0f;
#pragma unroll
        for (int j = 0; j < 4; j++) acc[i][j] = 0.0f;
    }

    const int ktiles = causal ? (qt + 1) : NKT;

    for (int kt = 0; kt < ktiles; kt++) {
        __syncthreads();
#pragma unroll
        for (int t = 0; t < 4; t++) {
            int s = tid + t * 256;
            int r = s >> 4;
            int c = (s & 15) << 2;
            float4 kv = *reinterpret_cast<const float4*>(
                &K[(kt * 64 + r) * DMODEL + h * DHEAD + c]);
            KP[c + 0][r] = kv.x;
            KP[c + 1][r] = kv.y;
            KP[c + 2][r] = kv.z;
            KP[c + 3][r] = kv.w;
            float4 vv = *reinterpret_cast<const float4*>(
                &V[(kt * 64 + r) * DMODEL + h * DHEAD + c]);
            *reinterpret_cast<float4*>(&Vs[r][c]) = vv;
        }
        __syncthreads();

        float sv[4][4];
#pragma unroll
        for (int i = 0; i < 4; i++)
#pragma unroll
            for (int j = 0; j < 4; j++) sv[i][j] = 0.0f;

#pragma unroll
        for (int d = 0; d < 64; d++) {
            float4 qa = *reinterpret_cast<const float4*>(&Qs[d][ty * 4]);
            float4 kb = *reinterpret_cast<const float4*>(&KP[d][tx * 4]);
            float qv[4] = {qa.x, qa.y, qa.z, qa.w};
            float kv[4] = {kb.x, kb.y, kb.z, kb.w};
#pragma unroll
            for (int i = 0; i < 4; i++)
#pragma unroll
                for (int j = 0; j < 4; j++)
                    sv[i][j] = fmaf(qv[i], kv[j], sv[i][j]);
        }

#pragma unroll
        for (int i = 0; i < 4; i++)
#pragma unroll
            for (int j = 0; j < 4; j++) sv[i][j] *= scale;

        if (causal && kt == qt) {
#pragma unroll
            for (int i = 0; i < 4; i++)
#pragma unroll
                for (int j = 0; j < 4; j++)
                    if (tx * 4 + j > ty * 4 + i) sv[i][j] = -1e30f;
        }

        float mnew[4];
#pragma unroll
        for (int i = 0; i < 4; i++)
            mnew[i] = fmaxf(fmaxf(sv[i][0], sv[i][1]), fmaxf(sv[i][2], sv[i][3]));
#pragma unroll
        for (int off = 8; off >= 1; off >>= 1) {
#pragma unroll
            for (int i = 0; i < 4; i++)
                mnew[i] = fmaxf(mnew[i], __shfl_xor_sync(0xffffffffu, mnew[i], off));
        }

        float alpha[4], rsum[4];
#pragma unroll
        for (int i = 0; i < 4; i++) {
            float mt = fmaxf(m_i[i], mnew[i]);
            alpha[i] = __expf(m_i[i] - mt);
            m_i[i] = mt;
            rsum[i] = 0.0f;
#pragma unroll
            for (int j = 0; j < 4; j++) {
                float p = __expf(sv[i][j] - mt);
                sv[i][j] = p;
                rsum[i] += p;
            }
        }
#pragma unroll
        for (int off = 8; off >= 1; off >>= 1) {
#pragma unroll
            for (int i = 0; i < 4; i++)
                rsum[i] += __shfl_xor_sync(0xffffffffu, rsum[i], off);
        }
#pragma unroll
        for (int i = 0; i < 4; i++) {
            l_i[i] = l_i[i] * alpha[i] + rsum[i];
#pragma unroll
            for (int j = 0; j < 4; j++) acc[i][j] *= alpha[i];
        }

        __syncthreads();
#pragma unroll
        for (int j = 0; j < 4; j++) {
            *reinterpret_cast<float4*>(&KP[tx * 4 + j][ty * 4]) =
                make_float4(sv[0][j], sv[1][j], sv[2][j], sv[3][j]);
        }
        __syncthreads();

#pragma unroll
        for (int k = 0; k < 64; k++) {
            float4 pa = *reinterpret_cast<const float4*>(&KP[k][ty * 4]);
            float4 vb = *reinterpret_cast<const float4*>(&Vs[k][tx * 4]);
            float pv[4] = {pa.x, pa.y, pa.z, pa.w};
            float vv[4] = {vb.x, vb.y, vb.z, vb.w};
#pragma unroll
            for (int i = 0; i < 4; i++)
#pragma unroll
                for (int j = 0; j < 4; j++)
                    acc[i][j] = fmaf(pv[i], vv[j], acc[i][j]);
        }
    }

#pragma unroll
    for (int i = 0; i < 4; i++) {
        float inv = 1.0f / l_i[i];
        float* Orow = O + (qt * 64 + ty * 4 + i) * DMODEL + h * DHEAD + tx * 4;
        *reinterpret_cast<float4*>(Orow) = make_float4(
            acc[i][0] * inv, acc[i][1] * inv, acc[i][2] * inv, acc[i][3] * inv);
    }
}

// ---------------------------------------------------------------------------
// Launch
// ---------------------------------------------------------------------------
extern "C" void kernel_launch(void* const* d_in, const int* in_sizes, int n_in,
                              void* d_out, int out_size) {
    const float* X  = (const float*)d_in[0];
    const float* Wq = (const float*)d_in[1];
    const float* Wk = (const float*)d_in[2];
    const float* Wv = (const float*)d_in[3];
    const float* Wo = (const float*)d_in[4];
    float* out = (float*)d_out;

    float *Qp, *Kp, *Vp, *Op;
    float2* ropep;
    __nv_bfloat16 *Ahp, *Alp, *Bthp, *Btlp;
    cudaGetSymbolAddress((void**)&Qp, g_Q);
    cudaGetSymbolAddress((void**)&Kp, g_K);
    cudaGetSymbolAddress((void**)&Vp, g_V);
    cudaGetSymbolAddress((void**)&Op, g_O);
    cudaGetSymbolAddress((void**)&ropep, g_rope);
    cudaGetSymbolAddress((void**)&Ahp, g_Ah);
    cudaGetSymbolAddress((void**)&Alp, g_Al);
    cudaGetSymbolAddress((void**)&Bthp, g_Bth);
    cudaGetSymbolAddress((void**)&Btlp, g_Btl);

    cudaFuncSetAttribute(gemm_mma, cudaFuncAttributeMaxDynamicSharedMemorySize,
                         GEMM_SMEM);

    dim3 gemm_grid(DMODEL / 128, LSEQ / 128);  // (8, 32)
    dim3 wt_grid(DMODEL / 32, DMODEL / 32);    // (32, 32)
    const int splitA_blocks = (LSEQ * DMODEL / 4) / 256;  // 4096

    split_kernel<<<splitA_blocks, 256>>>(X, Ahp, Alp);
    rope_table_kernel<<<512, 256>>>(ropep);

    wsplit_t_kernel<<<wt_grid, 256>>>(Wq, Bthp, Btlp);
    gemm_mma<<<gemm_grid, 256, GEMM_SMEM>>>(Ahp, Alp, Bthp, Btlp, Qp);

    wsplit_t_kernel<<<wt_grid, 256>>>(Wk, Bthp, Btlp);
    gemm_mma<<<gemm_grid, 256, GEMM_SMEM>>>(Ahp, Alp, Bthp, Btlp, Kp);

    wsplit_t_kernel<<<wt_grid, 256>>>(Wv, Bthp, Btlp);
    gemm_mma<<<gemm_grid, 256, GEMM_SMEM>>>(Ahp, Alp, Bthp, Btlp, Vp);

    rope_apply_kernel<<<LSEQ, 512>>>(Qp, Kp, ropep);

    dim3 attn_grid(LSEQ / 64, NHEAD);
    flash_kernel<<<attn_grid, 256>>>(Qp, Kp, Vp, Op);

    split_kernel<<<splitA_blocks, 256>>>(Op, Ahp, Alp);
    wsplit_t_kernel<<<wt_grid, 256>>>(Wo, Bthp, Btlp);
    gemm_mma<<<gemm_grid, 256, GEMM_SMEM>>>(Ahp, Alp, Bthp, Btlp, out);
}

// round 5
// speedup vs baseline: 3.2966x; 2.4147x over previous
#include <cuda_runtime.h>
#include <cuda_bf16.h>
#include <math.h>
#include <stdint.h>

// Problem constants
#define LSEQ 4096
#define DMODEL 1024
#define NHEAD 16
#define NAR 8
#define DHEAD 64
#define NCHUNK (DMODEL / 32)   // 32 K-chunks of 32 for GEMM

// ---------------------------------------------------------------------------
// Scratch (__device__ globals; no allocation allowed)
// ---------------------------------------------------------------------------
__device__ float g_Q[LSEQ * DMODEL];
__device__ float g_K[LSEQ * DMODEL];
__device__ float g_V[LSEQ * DMODEL];
__device__ float g_O[LSEQ * DMODEL];
__device__ __nv_bfloat16 g_Ah[LSEQ * DMODEL];    // split of A operand (X, then O)
__device__ __nv_bfloat16 g_Al[LSEQ * DMODEL];
__device__ __nv_bfloat16 g_Bth[DMODEL * DMODEL]; // transposed split weight [N,K]
__device__ __nv_bfloat16 g_Btl[DMODEL * DMODEL];
__device__ __nv_bfloat16 g_Qh[LSEQ * DMODEL];
__device__ __nv_bfloat16 g_Ql[LSEQ * DMODEL];
__device__ __nv_bfloat16 g_Kh[LSEQ * DMODEL];
__device__ __nv_bfloat16 g_Kl[LSEQ * DMODEL];
__device__ __nv_bfloat16 g_Vh[LSEQ * DMODEL];
__device__ __nv_bfloat16 g_Vl[LSEQ * DMODEL];
__device__ float2 g_rope[LSEQ * 32];             // cos/sin table

// ---------------------------------------------------------------------------
// PTX helpers (base sm_103-safe: mma.sync / ldmatrix / cp.async only)
// ---------------------------------------------------------------------------
__device__ __forceinline__ uint32_t smem_u32(const void* p) {
    uint32_t a;
    asm("{ .reg .u64 t; cvta.to.shared.u64 t, %1; cvt.u32.u64 %0, t; }"
        : "=r"(a) : "l"(p));
    return a;
}

#define CP16(dst, src) \
    asm volatile("cp.async.cg.shared.global [%0], [%1], 16;" \
                 :: "r"(dst), "l"(src) : "memory")
#define CP_COMMIT() asm volatile("cp.async.commit_group;" ::: "memory")

__device__ __forceinline__ void ldsm4(uint32_t* r, uint32_t addr) {
    asm volatile("ldmatrix.sync.aligned.m8n8.x4.shared.b16 {%0,%1,%2,%3}, [%4];"
                 : "=r"(r[0]), "=r"(r[1]), "=r"(r[2]), "=r"(r[3]) : "r"(addr));
}
__device__ __forceinline__ void ldsm4t(uint32_t* r, uint32_t addr) {
    asm volatile("ldmatrix.sync.aligned.m8n8.x4.trans.shared.b16 {%0,%1,%2,%3}, [%4];"
                 : "=r"(r[0]), "=r"(r[1]), "=r"(r[2]), "=r"(r[3]) : "r"(addr));
}

#define MMA16816(d, a, b)                                                       \
    asm volatile(                                                               \
        "mma.sync.aligned.m16n8k16.row.col.f32.bf16.bf16.f32 "                  \
        "{%0,%1,%2,%3}, {%4,%5,%6,%7}, {%8,%9}, {%0,%1,%2,%3};"                 \
        : "+f"((d)[0]), "+f"((d)[1]), "+f"((d)[2]), "+f"((d)[3])                \
        : "r"((a)[0]), "r"((a)[1]), "r"((a)[2]), "r"((a)[3]),                   \
          "r"((b)[0]), "r"((b)[1]))

// GEMM swizzle: rows of 32 bf16 (64B), 4 chunks of 16B
__device__ __forceinline__ uint32_t swz(int row, int chunk) {
    return (uint32_t)(row * 64 + ((chunk ^ ((row >> 1) & 3)) << 4));
}
// Flash swizzle: rows of 64 bf16 (128B), 8 chunks of 16B
__device__ __forceinline__ uint32_t swz8(int row, int chunk) {
    return (uint32_t)(row * 128 + ((chunk ^ (row & 7)) << 4));
}

__device__ __forceinline__ uint32_t pack_bf16x2(float lo, float hi) {
    uint32_t d;
    asm("cvt.rn.bf16x2.f32 %0, %1, %2;" : "=r"(d) : "f"(hi), "f"(lo));
    return d;
}

// ---------------------------------------------------------------------------
// Split kernel: fp32 -> (bf16 hi, bf16 lo)
// ---------------------------------------------------------------------------
__global__ void __launch_bounds__(256) split_kernel(const float* __restrict__ src,
                                                    __nv_bfloat16* __restrict__ hi,
                                                    __nv_bfloat16* __restrict__ lo) {
    int idx = blockIdx.x * 256 + threadIdx.x;  // over float4s
    float4 v = reinterpret_cast<const float4*>(src)[idx];
    float x[4] = {v.x, v.y, v.z, v.w};
    __nv_bfloat16 h[4], l[4];
#pragma unroll
    for (int i = 0; i < 4; i++) {
        h[i] = __float2bfloat16(x[i]);
        l[i] = __float2bfloat16(x[i] - __bfloat162float(h[i]));
    }
    reinterpret_cast<__nv_bfloat162*>(hi)[idx * 2 + 0] = __nv_bfloat162(h[0], h[1]);
    reinterpret_cast<__nv_bfloat162*>(hi)[idx * 2 + 1] = __nv_bfloat162(h[2], h[3]);
    reinterpret_cast<__nv_bfloat162*>(lo)[idx * 2 + 0] = __nv_bfloat162(l[0], l[1]);
    reinterpret_cast<__nv_bfloat162*>(lo)[idx * 2 + 1] = __nv_bfloat162(l[2], l[3]);
}

// ---------------------------------------------------------------------------
// Transpose+split: W[K,N] fp32 -> Bt_hi/Bt_lo [N,K] bf16
// ---------------------------------------------------------------------------
__global__ void __launch_bounds__(256) wsplit_t_kernel(const float* __restrict__ W,
                                                       __nv_bfloat16* __restrict__ bth,
                                                       __nv_bfloat16* __restrict__ btl) {
    __shared__ float s[32][33];
    int tx = threadIdx.x & 31, ty = threadIdx.x >> 5;
    int n0 = blockIdx.x * 32, k0 = blockIdx.y * 32;
#pragma unroll
    for (int j = 0; j < 4; j++)
        s[ty + j * 8][tx] = W[(k0 + ty + j * 8) * DMODEL + n0 + tx];
    __syncthreads();
#pragma unroll
    for (int j = 0; j < 4; j++) {
        float x = s[tx][ty + j * 8];
        __nv_bfloat16 h = __float2bfloat16(x);
        __nv_bfloat16 l = __float2bfloat16(x - __bfloat162float(h));
        int o = (n0 + ty + j * 8) * DMODEL + k0 + tx;
        bth[o] = h;
        btl[o] = l;
    }
}

// ---------------------------------------------------------------------------
// HMMA GEMM (unchanged, validated in R4)
// ---------------------------------------------------------------------------
#define GEMM_SMEM 65536

__global__ void __launch_bounds__(256) gemm_mma(const __nv_bfloat16* __restrict__ Ah,
                                                const __nv_bfloat16* __restrict__ Al,
                                                const __nv_bfloat16* __restrict__ Bh,
                                                const __nv_bfloat16* __restrict__ Bl,
                                                float* __restrict__ C) {
    extern __shared__ char sm[];
    const uint32_t sb = smem_u32(sm);
    const int tid = threadIdx.x;
    const int wid = tid >> 5, lane = tid & 31;
    const int m0 = blockIdx.y << 7;
    const int n0 = blockIdx.x << 7;
    const int wm = (wid & 3) * 32;
    const int wn = (wid >> 2) * 64;

    const int cr = tid >> 1;
    const int cbase = (tid & 1) << 1;

    float acc[2][8][4];
#pragma unroll
    for (int a = 0; a < 2; a++)
#pragma unroll
        for (int n = 0; n < 8; n++)
#pragma unroll
            for (int j = 0; j < 4; j++) acc[a][n][j] = 0.0f;

#define ISSUE(chunk, buf)                                                        \
    do {                                                                         \
        const int _k0 = (chunk) * 32;                                            \
        const uint32_t _sbb = sb + (buf) * 32768u;                               \
        _Pragma("unroll")                                                        \
        for (int _j = 0; _j < 2; _j++) {                                         \
            const int _cc = cbase + _j;                                          \
            const uint32_t _so = swz(cr, _cc);                                   \
            const size_t _ea = (size_t)(m0 + cr) * DMODEL + _k0 + _cc * 8;       \
            const size_t _eb = (size_t)(n0 + cr) * DMODEL + _k0 + _cc * 8;       \
            CP16(_sbb + _so,          (const void*)(Ah + _ea));                  \
            CP16(_sbb + 8192u + _so,  (const void*)(Al + _ea));                  \
            CP16(_sbb + 16384u + _so, (const void*)(Bh + _eb));                  \
            CP16(_sbb + 24576u + _so, (const void*)(Bl + _eb));                  \
        }                                                                        \
    } while (0)

    ISSUE(0, 0);
    CP_COMMIT();
    ISSUE(1, 1);
    CP_COMMIT();

#pragma unroll 1
    for (int c = 0; c < NCHUNK; c++) {
        if (c < NCHUNK - 1)
            asm volatile("cp.async.wait_group 1;" ::: "memory");
        else
            asm volatile("cp.async.wait_group 0;" ::: "memory");
        __syncthreads();

        const uint32_t ab = sb + (c & 1) * 32768u;
        const uint32_t bbb = ab + 16384u;

#pragma unroll
        for (int ks = 0; ks < 2; ks++) {
            uint32_t ah[2][4], al[2][4];
#pragma unroll
            for (int a = 0; a < 2; a++) {
                const int row = wm + a * 16 + ((lane >> 3) & 1) * 8 + (lane & 7);
                const int ch = ks * 2 + (lane >> 4);
                const uint32_t off = swz(row, ch);
                ldsm4(ah[a], ab + off);
                ldsm4(al[a], ab + 8192u + off);
            }
#pragma unroll
            for (int g = 0; g < 4; g++) {
                const int row = wn + g * 16 + ((lane >> 4) & 1) * 8 + (lane & 7);
                const int ch = ks * 2 + ((lane >> 3) & 1);
                const uint32_t off = swz(row, ch);
                uint32_t bh[4], bl[4];
                ldsm4(bh, bbb + off);
#pragma unroll
                for (int a = 0; a < 2; a++) {
                    MMA16816(acc[a][2 * g + 0], ah[a], bh + 0);
                    MMA16816(acc[a][2 * g + 1], ah[a], bh + 2);
                    MMA16816(acc[a][2 * g + 0], al[a], bh + 0);
                    MMA16816(acc[a][2 * g + 1], al[a], bh + 2);
                }
                ldsm4(bl, bbb + 8192u + off);
#pragma unroll
                for (int a = 0; a < 2; a++) {
                    MMA16816(acc[a][2 * g + 0], ah[a], bl + 0);
                    MMA16816(acc[a][2 * g + 1], ah[a], bl + 2);
                }
            }
        }
        __syncthreads();

        if (c + 2 < NCHUNK) {
            ISSUE(c + 2, c & 1);
            CP_COMMIT();
        }
    }
#undef ISSUE

    const int er = lane >> 2;
    const int ec = (lane & 3) * 2;
#pragma unroll
    for (int a = 0; a < 2; a++) {
#pragma unroll
        for (int n = 0; n < 8; n++) {
            float* p0 = C + (size_t)(m0 + wm + a * 16 + er) * DMODEL + n0 + wn + n * 8 + ec;
            float* p1 = p0 + 8 * DMODEL;
            *reinterpret_cast<float2*>(p0) = make_float2(acc[a][n][0], acc[a][n][1]);
            *reinterpret_cast<float2*>(p1) = make_float2(acc[a][n][2], acc[a][n][3]);
        }
    }
}

// ---------------------------------------------------------------------------
// RoPE: table precompute
// ---------------------------------------------------------------------------
__global__ void __launch_bounds__(256) rope_table_kernel(float2* __restrict__ tab) {
    int idx = blockIdx.x * 256 + threadIdx.x;  // 131072
    int row = idx >> 5, jj = idx & 31;
    float invf = (float)pow(10000.0, -(double)jj / 32.0);
    float ang = (float)row * invf;  // fp32 product like jax
    double s, c;
    sincos((double)ang, &s, &c);
    tab[idx] = make_float2((float)c, (float)s);
}

// RoPE apply + bf16 split of Q,K in one pass
__global__ void __launch_bounds__(512) rope_split_kernel(
    const float* __restrict__ Q, const float* __restrict__ K,
    const float2* __restrict__ tab,
    __nv_bfloat16* __restrict__ Qh, __nv_bfloat16* __restrict__ Ql,
    __nv_bfloat16* __restrict__ Kh, __nv_bfloat16* __restrict__ Kl) {
    int idx = blockIdx.x * 512 + threadIdx.x;
    int row = idx >> 9;
    int rem = idx & 511;
    int h = rem >> 5;
    int jj = rem & 31;

    float2 cs2 = tab[(row << 5) | jj];
    float cs = cs2.x, sn = cs2.y;
    int base = row * DMODEL + h * DHEAD;

    float q1 = Q[base + jj], q2 = Q[base + jj + 32];
    float r1 = fmaf(q1, cs, -q2 * sn);
    float r2 = fmaf(q2, cs, q1 * sn);
    __nv_bfloat16 h1 = __float2bfloat16(r1);
    __nv_bfloat16 h2 = __float2bfloat16(r2);
    Qh[base + jj] = h1;
    Qh[base + jj + 32] = h2;
    Ql[base + jj] = __float2bfloat16(r1 - __bfloat162float(h1));
    Ql[base + jj + 32] = __float2bfloat16(r2 - __bfloat162float(h2));

    float k1 = K[base + jj], k2 = K[base + jj + 32];
    r1 = fmaf(k1, cs, -k2 * sn);
    r2 = fmaf(k2, cs, k1 * sn);
    h1 = __float2bfloat16(r1);
    h2 = __float2bfloat16(r2);
    Kh[base + jj] = h1;
    Kh[base + jj + 32] = h2;
    Kl[base + jj] = __float2bfloat16(r1 - __bfloat162float(h1));
    Kl[base + jj + 32] = __float2bfloat16(r2 - __bfloat162float(h2));
}

// ---------------------------------------------------------------------------
// HMMA flash attention.
// grid = (32 q-tiles of 128, 16 heads), 128 threads (4 warps, 32 q-rows each).
// kv tiles of 64, cp.async double-buffered Kh/Kl/Vh/Vl stages.
// Splits: S = QhKh + QhKl + QlKh;  O += PhVh + PhVl + PlVh.
// smem: Qh(16K) Ql(16K) + 2 stages x (Kh,Kl,Vh,Vl 8K each) = 96KB.
// ---------------------------------------------------------------------------
#define FLASH_SMEM 98304

__global__ void __launch_bounds__(128) flash_mma(
    const __nv_bfloat16* __restrict__ Qh, const __nv_bfloat16* __restrict__ Ql,
    const __nv_bfloat16* __restrict__ Kh, const __nv_bfloat16* __restrict__ Kl,
    const __nv_bfloat16* __restrict__ Vh, const __nv_bfloat16* __restrict__ Vl,
    float* __restrict__ O) {
    extern __shared__ char sm[];
    const uint32_t sb = smem_u32(sm);
    const int tid = threadIdx.x;
    const int wid = tid >> 5, lane = tid & 31;
    const int qt = blockIdx.x;
    const int h = blockIdx.y;
    const bool causal = (h < NAR);
    const int wm = wid * 32;

    // ---- load Q tile (rows qt*128..+127, head slice), both splits ----
    {
        const int row = tid;  // 128 threads = 128 rows
        const size_t g = (size_t)(qt * 128 + row) * DMODEL + h * DHEAD;
#pragma unroll
        for (int ch = 0; ch < 8; ch++) {
            const uint32_t so = swz8(row, ch);
            CP16(sb + so, (const void*)(Qh + g + ch * 8));
            CP16(sb + 16384u + so, (const void*)(Ql + g + ch * 8));
        }
    }
    CP_COMMIT();

    const int ktiles = causal ? (2 * qt + 2) : (LSEQ / 64);

#define ISSUEKV(kt, buf)                                                        \
    do {                                                                        \
        const int _row = tid >> 1;                                              \
        const int _cb = (tid & 1) * 4;                                          \
        const uint32_t _sbb = sb + 32768u + (buf) * 32768u;                     \
        const size_t _g = (size_t)((kt) * 64 + _row) * DMODEL + h * DHEAD;      \
        _Pragma("unroll")                                                       \
        for (int _j = 0; _j < 4; _j++) {                                        \
            const uint32_t _so = swz8(_row, _cb + _j);                          \
            const size_t _e = _g + (_cb + _j) * 8;                              \
            CP16(_sbb + _so,           (const void*)(Kh + _e));                 \
            CP16(_sbb + 8192u + _so,   (const void*)(Kl + _e));                 \
            CP16(_sbb + 16384u + _so,  (const void*)(Vh + _e));                 \
            CP16(_sbb + 24576u + _so,  (const void*)(Vl + _e));                 \
        }                                                                       \
    } while (0)

    ISSUEKV(0, 0);
    CP_COMMIT();
    ISSUEKV(1, 1);
    CP_COMMIT();

    float o[2][8][4];
#pragma unroll
    for (int a = 0; a < 2; a++)
#pragma unroll
        for (int n = 0; n < 8; n++)
#pragma unroll
            for (int j = 0; j < 4; j++) o[a][n][j] = 0.0f;
    float m_[4] = {-1e30f, -1e30f, -1e30f, -1e30f};
    float l_[4] = {0.0f, 0.0f, 0.0f, 0.0f};

#pragma unroll 1
    for (int kt = 0; kt < ktiles; kt++) {
        if (kt < ktiles - 1)
            asm volatile("cp.async.wait_group 1;" ::: "memory");
        else
            asm volatile("cp.async.wait_group 0;" ::: "memory");
        __syncthreads();

        const uint32_t kbase = sb + 32768u + (kt & 1) * 32768u;
        const uint32_t vbase = kbase + 16384u;

        // ---- S = Q K^T (3 split terms) ----
        float sv[2][8][4];
#pragma unroll
        for (int a = 0; a < 2; a++)
#pragma unroll
            for (int n = 0; n < 8; n++)
#pragma unroll
                for (int j = 0; j < 4; j++) sv[a][n][j] = 0.0f;

#pragma unroll
        for (int ks = 0; ks < 4; ks++) {
            uint32_t ah[2][4], al[2][4];
#pragma unroll
            for (int mf = 0; mf < 2; mf++) {
                const int row = wm + mf * 16 + ((lane >> 3) & 1) * 8 + (lane & 7);
                const int ch = ks * 2 + (lane >> 4);
                const uint32_t off = swz8(row, ch);
                ldsm4(ah[mf], sb + off);
                ldsm4(al[mf], sb + 16384u + off);
            }
#pragma unroll
            for (int g = 0; g < 4; g++) {
                const int krow = g * 16 + ((lane >> 4) & 1) * 8 + (lane & 7);
                const int kch = ks * 2 + ((lane >> 3) & 1);
                const uint32_t off = swz8(krow, kch);
                uint32_t kh[4], kl[4];
                ldsm4(kh, kbase + off);
#pragma unroll
                for (int mf = 0; mf < 2; mf++) {
                    MMA16816(sv[mf][2 * g + 0], ah[mf], kh + 0);
                    MMA16816(sv[mf][2 * g + 1], ah[mf], kh + 2);
                    MMA16816(sv[mf][2 * g + 0], al[mf], kh + 0);
                    MMA16816(sv[mf][2 * g + 1], al[mf], kh + 2);
                }
                ldsm4(kl, kbase + 8192u + off);
#pragma unroll
                for (int mf = 0; mf < 2; mf++) {
                    MMA16816(sv[mf][2 * g + 0], ah[mf], kl + 0);
                    MMA16816(sv[mf][2 * g + 1], ah[mf], kl + 2);
                }
            }
        }

        // ---- scale + causal mask ----
#pragma unroll
        for (int mf = 0; mf < 2; mf++)
#pragma unroll
            for (int nf = 0; nf < 8; nf++)
#pragma unroll
                for (int j = 0; j < 4; j++) sv[mf][nf][j] *= 0.125f;

        if (causal && kt >= 2 * qt) {
#pragma unroll
            for (int mf = 0; mf < 2; mf++) {
#pragma unroll
                for (int half = 0; half < 2; half++) {
                    const int qg = qt * 128 + wm + mf * 16 + (lane >> 2) + half * 8;
#pragma unroll
                    for (int nf = 0; nf < 8; nf++) {
#pragma unroll
                        for (int j = 0; j < 2; j++) {
                            const int kv = kt * 64 + nf * 8 + (lane & 3) * 2 + j;
                            if (kv > qg) sv[mf][nf][half * 2 + j] = -1e30f;
                        }
                    }
                }
            }
        }

        // ---- online softmax (rows: r = mf*2 + half) ----
        float mnew[4];
#pragma unroll
        for (int mf = 0; mf < 2; mf++) {
#pragma unroll
            for (int half = 0; half < 2; half++) {
                float mx = -1e30f;
#pragma unroll
                for (int nf = 0; nf < 8; nf++)
                    mx = fmaxf(mx, fmaxf(sv[mf][nf][half * 2], sv[mf][nf][half * 2 + 1]));
                mnew[mf * 2 + half] = mx;
            }
        }
#pragma unroll
        for (int r = 0; r < 4; r++) {
            mnew[r] = fmaxf(mnew[r], __shfl_xor_sync(0xffffffffu, mnew[r], 1));
            mnew[r] = fmaxf(mnew[r], __shfl_xor_sync(0xffffffffu, mnew[r], 2));
        }

        float alpha[4];
#pragma unroll
        for (int r = 0; r < 4; r++) {
            float mt = fmaxf(m_[r], mnew[r]);
            alpha[r] = __expf(m_[r] - mt);
            m_[r] = mt;
        }

        float rsum[4] = {0.0f, 0.0f, 0.0f, 0.0f};
#pragma unroll
        for (int mf = 0; mf < 2; mf++) {
#pragma unroll
            for (int nf = 0; nf < 8; nf++) {
#pragma unroll
                for (int half = 0; half < 2; half++) {
#pragma unroll
                    for (int j = 0; j < 2; j++) {
                        float p = __expf(sv[mf][nf][half * 2 + j] - m_[mf * 2 + half]);
                        sv[mf][nf][half * 2 + j] = p;
                        rsum[mf * 2 + half] += p;
                    }
                }
            }
        }
#pragma unroll
        for (int r = 0; r < 4; r++) {
            rsum[r] += __shfl_xor_sync(0xffffffffu, rsum[r], 1);
            rsum[r] += __shfl_xor_sync(0xffffffffu, rsum[r], 2);
            l_[r] = l_[r] * alpha[r] + rsum[r];
        }
#pragma unroll
        for (int mf = 0; mf < 2; mf++)
#pragma unroll
            for (int nf = 0; nf < 8; nf++)
#pragma unroll
                for (int half = 0; half < 2; half++) {
                    o[mf][nf][half * 2 + 0] *= alpha[mf * 2 + half];
                    o[mf][nf][half * 2 + 1] *= alpha[mf * 2 + half];
                }

        // ---- O += P V (3 split terms); P A-frags built in registers ----
#pragma unroll
        for (int kg = 0; kg < 4; kg++) {
            uint32_t ph[2][4], pl[2][4];
#pragma unroll
            for (int mf = 0; mf < 2; mf++) {
#pragma unroll
                for (int q = 0; q < 2; q++) {      // q=0: nf=2kg (k0-7), q=1: nf=2kg+1 (k8-15)
                    const int nf = 2 * kg + q;
#pragma unroll
                    for (int half = 0; half < 2; half++) {
                        float p0 = sv[mf][nf][half * 2 + 0];
                        float p1 = sv[mf][nf][half * 2 + 1];
                        __nv_bfloat16 b0 = __float2bfloat16(p0);
                        __nv_bfloat16 b1 = __float2bfloat16(p1);
                        float r0 = p0 - __bfloat162float(b0);
                        float r1 = p1 - __bfloat162float(b1);
                        __nv_bfloat162 hp(b0, b1);
                        ph[mf][q * 2 + half] = *reinterpret_cast<uint32_t*>(&hp);
                        pl[mf][q * 2 + half] = pack_bf16x2(r0, r1);
                    }
                }
            }
#pragma unroll
            for (int gd = 0; gd < 4; gd++) {
                const int vrow = kg * 16 + (lane & 15);
                const int vch = gd * 2 + (lane >> 4);
                const uint32_t off = swz8(vrow, vch);
                uint32_t vh[4], vl[4];
                ldsm4t(vh, vbase + off);
#pragma unroll
                for (int mf = 0; mf < 2; mf++) {
                    MMA16816(o[mf][2 * gd + 0], ph[mf], vh + 0);
                    MMA16816(o[mf][2 * gd + 1], ph[mf], vh + 2);
                    MMA16816(o[mf][2 * gd + 0], pl[mf], vh + 0);
                    MMA16816(o[mf][2 * gd + 1], pl[mf], vh + 2);
                }
                ldsm4t(vl, vbase + 8192u + off);
#pragma unroll
                for (int mf = 0; mf < 2; mf++) {
                    MMA16816(o[mf][2 * gd + 0], ph[mf], vl + 0);
                    MMA16816(o[mf][2 * gd + 1], ph[mf], vl + 2);
                }
            }
        }

        __syncthreads();
        if (kt + 2 < ktiles) {
            ISSUEKV(kt + 2, kt & 1);
            CP_COMMIT();
        }
    }
#undef ISSUEKV

    // ---- epilogue: normalize and store fp32 O ----
#pragma unroll
    for (int mf = 0; mf < 2; mf++) {
        const int rowa = qt * 128 + wm + mf * 16 + (lane >> 2);
        const float inva = 1.0f / l_[mf * 2];
        const float invb = 1.0f / l_[mf * 2 + 1];
#pragma unroll
        for (int nf = 0; nf < 8; nf++) {
            const int col = h * DHEAD + nf * 8 + (lane & 3) * 2;
            float* p0 = O + (size_t)rowa * DMODEL + col;
            float* p1 = p0 + 8 * DMODEL;
            *reinterpret_cast<float2*>(p0) =
                make_float2(o[mf][nf][0] * inva, o[mf][nf][1] * inva);
            *reinterpret_cast<float2*>(p1) =
                make_float2(o[mf][nf][2] * invb, o[mf][nf][3] * invb);
        }
    }
}

// ---------------------------------------------------------------------------
// Launch
// ---------------------------------------------------------------------------
extern "C" void kernel_launch(void* const* d_in, const int* in_sizes, int n_in,
                              void* d_out, int out_size) {
    const float* X  = (const float*)d_in[0];
    const float* Wq = (const float*)d_in[1];
    const float* Wk = (const float*)d_in[2];
    const float* Wv = (const float*)d_in[3];
    const float* Wo = (const float*)d_in[4];
    float* out = (float*)d_out;

    float *Qp, *Kp, *Vp, *Op;
    float2* ropep;
    __nv_bfloat16 *Ahp, *Alp, *Bthp, *Btlp;
    __nv_bfloat16 *Qhp, *Qlp, *Khp, *Klp, *Vhp, *Vlp;
    cudaGetSymbolAddress((void**)&Qp, g_Q);
    cudaGetSymbolAddress((void**)&Kp, g_K);
    cudaGetSymbolAddress((void**)&Vp, g_V);
    cudaGetSymbolAddress((void**)&Op, g_O);
    cudaGetSymbolAddress((void**)&ropep, g_rope);
    cudaGetSymbolAddress((void**)&Ahp, g_Ah);
    cudaGetSymbolAddress((void**)&Alp, g_Al);
    cudaGetSymbolAddress((void**)&Bthp, g_Bth);
    cudaGetSymbolAddress((void**)&Btlp, g_Btl);
    cudaGetSymbolAddress((void**)&Qhp, g_Qh);
    cudaGetSymbolAddress((void**)&Qlp, g_Ql);
    cudaGetSymbolAddress((void**)&Khp, g_Kh);
    cudaGetSymbolAddress((void**)&Klp, g_Kl);
    cudaGetSymbolAddress((void**)&Vhp, g_Vh);
    cudaGetSymbolAddress((void**)&Vlp, g_Vl);

    cudaFuncSetAttribute(gemm_mma, cudaFuncAttributeMaxDynamicSharedMemorySize,
                         GEMM_SMEM);
    cudaFuncSetAttribute(flash_mma, cudaFuncAttributeMaxDynamicSharedMemorySize,
                         FLASH_SMEM);

    dim3 gemm_grid(DMODEL / 128, LSEQ / 128);  // (8, 32)
    dim3 wt_grid(DMODEL / 32, DMODEL / 32);    // (32, 32)
    const int splitA_blocks = (LSEQ * DMODEL / 4) / 256;  // 4096

    split_kernel<<<splitA_blocks, 256>>>(X, Ahp, Alp);
    rope_table_kernel<<<512, 256>>>(ropep);

    wsplit_t_kernel<<<wt_grid, 256>>>(Wq, Bthp, Btlp);
    gemm_mma<<<gemm_grid, 256, GEMM_SMEM>>>(Ahp, Alp, Bthp, Btlp, Qp);

    wsplit_t_kernel<<<wt_grid, 256>>>(Wk, Bthp, Btlp);
    gemm_mma<<<gemm_grid, 256, GEMM_SMEM>>>(Ahp, Alp, Bthp, Btlp, Kp);

    wsplit_t_kernel<<<wt_grid, 256>>>(Wv, Bthp, Btlp);
    gemm_mma<<<gemm_grid, 256, GEMM_SMEM>>>(Ahp, Alp, Bthp, Btlp, Vp);

    // RoPE + split Q,K ; split V
    rope_split_kernel<<<LSEQ, 512>>>(Qp, Kp, ropep, Qhp, Qlp, Khp, Klp);
    split_kernel<<<splitA_blocks, 256>>>(Vp, Vhp, Vlp);

    dim3 attn_grid(LSEQ / 128, NHEAD);  // (32, 16)
    flash_mma<<<attn_grid, 128, FLASH_SMEM>>>(Qhp, Qlp, Khp, Klp, Vhp, Vlp, Op);

    split_kernel<<<splitA_blocks, 256>>>(Op, Ahp, Alp);
    wsplit_t_kernel<<<wt_grid, 256>>>(Wo, Bthp, Btlp);
    gemm_mma<<<gemm_grid, 256, GEMM_SMEM>>>(Ahp, Alp, Bthp, Btlp, out);
}

// round 6
// speedup vs baseline: 3.4990x; 1.0614x over previous
#include <cuda_runtime.h>
#include <cuda_bf16.h>
#include <math.h>
#include <stdint.h>

// Problem constants
#define LSEQ 4096
#define DMODEL 1024
#define NHEAD 16
#define NAR 8
#define DHEAD 64
#define NCHUNK (DMODEL / 32)   // 32 K-chunks of 32 for GEMM

// ---------------------------------------------------------------------------
// Scratch (__device__ globals; no allocation allowed)
// ---------------------------------------------------------------------------
__device__ __nv_bfloat16 g_Ah[LSEQ * DMODEL];      // split of A operand (X, then O)
__device__ __nv_bfloat16 g_Al[LSEQ * DMODEL];
__device__ __nv_bfloat16 g_Bth[3 * DMODEL * DMODEL]; // transposed split weights [N,K]
__device__ __nv_bfloat16 g_Btl[3 * DMODEL * DMODEL];
__device__ __nv_bfloat16 g_Qh[LSEQ * DMODEL];
__device__ __nv_bfloat16 g_Ql[LSEQ * DMODEL];
__device__ __nv_bfloat16 g_Kh[LSEQ * DMODEL];
__device__ __nv_bfloat16 g_Kl[LSEQ * DMODEL];
__device__ __nv_bfloat16 g_Vh[LSEQ * DMODEL];
__device__ __nv_bfloat16 g_Vl[LSEQ * DMODEL];
__device__ float2 g_rope[LSEQ * 32];               // cos/sin table

// ---------------------------------------------------------------------------
// PTX helpers (base sm_103-safe: mma.sync / ldmatrix / cp.async only)
// ---------------------------------------------------------------------------
__device__ __forceinline__ uint32_t smem_u32(const void* p) {
    uint32_t a;
    asm("{ .reg .u64 t; cvta.to.shared.u64 t, %1; cvt.u32.u64 %0, t; }"
        : "=r"(a) : "l"(p));
    return a;
}

#define CP16(dst, src) \
    asm volatile("cp.async.cg.shared.global [%0], [%1], 16;" \
                 :: "r"(dst), "l"(src) : "memory")
#define CP_COMMIT() asm volatile("cp.async.commit_group;" ::: "memory")

__device__ __forceinline__ void ldsm4(uint32_t* r, uint32_t addr) {
    asm volatile("ldmatrix.sync.aligned.m8n8.x4.shared.b16 {%0,%1,%2,%3}, [%4];"
                 : "=r"(r[0]), "=r"(r[1]), "=r"(r[2]), "=r"(r[3]) : "r"(addr));
}
__device__ __forceinline__ void ldsm4t(uint32_t* r, uint32_t addr) {
    asm volatile("ldmatrix.sync.aligned.m8n8.x4.trans.shared.b16 {%0,%1,%2,%3}, [%4];"
                 : "=r"(r[0]), "=r"(r[1]), "=r"(r[2]), "=r"(r[3]) : "r"(addr));
}

#define MMA16816(d, a, b)                                                       \
    asm volatile(                                                               \
        "mma.sync.aligned.m16n8k16.row.col.f32.bf16.bf16.f32 "                  \
        "{%0,%1,%2,%3}, {%4,%5,%6,%7}, {%8,%9}, {%0,%1,%2,%3};"                 \
        : "+f"((d)[0]), "+f"((d)[1]), "+f"((d)[2]), "+f"((d)[3])                \
        : "r"((a)[0]), "r"((a)[1]), "r"((a)[2]), "r"((a)[3]),                   \
          "r"((b)[0]), "r"((b)[1]))

// GEMM swizzle: rows of 32 bf16 (64B), 4 chunks of 16B
__device__ __forceinline__ uint32_t swz(int row, int chunk) {
    return (uint32_t)(row * 64 + ((chunk ^ ((row >> 1) & 3)) << 4));
}
// Flash swizzle: rows of 64 bf16 (128B), 8 chunks of 16B
__device__ __forceinline__ uint32_t swz8(int row, int chunk) {
    return (uint32_t)(row * 128 + ((chunk ^ (row & 7)) << 4));
}

__device__ __forceinline__ uint32_t pack_bf16x2(float lo, float hi) {
    uint32_t d;
    asm("cvt.rn.bf16x2.f32 %0, %1, %2;" : "=r"(d) : "f"(hi), "f"(lo));
    return d;
}

// Split one fp32 to hi/lo bf16 pair
__device__ __forceinline__ void split2(float x0, float x1,
                                       uint32_t& h, uint32_t& l) {
    __nv_bfloat16 h0 = __float2bfloat16(x0);
    __nv_bfloat16 h1 = __float2bfloat16(x1);
    __nv_bfloat162 hp(h0, h1);
    h = *reinterpret_cast<uint32_t*>(&hp);
    l = pack_bf16x2(x0 - __bfloat162float(h0), x1 - __bfloat162float(h1));
}

// ---------------------------------------------------------------------------
// Split kernel: fp32 -> (bf16 hi, bf16 lo)  (used for X only)
// ---------------------------------------------------------------------------
__global__ void __launch_bounds__(256) split_kernel(const float* __restrict__ src,
                                                    __nv_bfloat16* __restrict__ hi,
                                                    __nv_bfloat16* __restrict__ lo) {
    int idx = blockIdx.x * 256 + threadIdx.x;  // over float4s
    float4 v = reinterpret_cast<const float4*>(src)[idx];
    float x[4] = {v.x, v.y, v.z, v.w};
    __nv_bfloat16 h[4], l[4];
#pragma unroll
    for (int i = 0; i < 4; i++) {
        h[i] = __float2bfloat16(x[i]);
        l[i] = __float2bfloat16(x[i] - __bfloat162float(h[i]));
    }
    reinterpret_cast<__nv_bfloat162*>(hi)[idx * 2 + 0] = __nv_bfloat162(h[0], h[1]);
    reinterpret_cast<__nv_bfloat162*>(hi)[idx * 2 + 1] = __nv_bfloat162(h[2], h[3]);
    reinterpret_cast<__nv_bfloat162*>(lo)[idx * 2 + 0] = __nv_bfloat162(l[0], l[1]);
    reinterpret_cast<__nv_bfloat162*>(lo)[idx * 2 + 1] = __nv_bfloat162(l[2], l[3]);
}

// ---------------------------------------------------------------------------
// Transpose+split: W[K,N] fp32 -> Bt_hi/Bt_lo [N,K] bf16
// ---------------------------------------------------------------------------
__global__ void __launch_bounds__(256) wsplit_t_kernel(const float* __restrict__ W,
                                                       __nv_bfloat16* __restrict__ bth,
                                                       __nv_bfloat16* __restrict__ btl) {
    __shared__ float s[32][33];
    int tx = threadIdx.x & 31, ty = threadIdx.x >> 5;
    int n0 = blockIdx.x * 32, k0 = blockIdx.y * 32;
#pragma unroll
    for (int j = 0; j < 4; j++)
        s[ty + j * 8][tx] = W[(k0 + ty + j * 8) * DMODEL + n0 + tx];
    __syncthreads();
#pragma unroll
    for (int j = 0; j < 4; j++) {
        float x = s[tx][ty + j * 8];
        __nv_bfloat16 h = __float2bfloat16(x);
        __nv_bfloat16 l = __float2bfloat16(x - __bfloat162float(h));
        int o = (n0 + ty + j * 8) * DMODEL + k0 + tx;
        bth[o] = h;
        btl[o] = l;
    }
}

// ---------------------------------------------------------------------------
// Shared GEMM mainloop (validated R4): accumulates 128x128 tile into acc.
// ---------------------------------------------------------------------------
#define GEMM_SMEM 65536

#define GEMM_MAINLOOP(Ah_, Al_, Bh_, Bl_)                                        \
    const uint32_t sb = smem_u32(sm);                                            \
    const int tid = threadIdx.x;                                                 \
    const int wid = tid >> 5, lane = tid & 31;                                   \
    const int m0 = blockIdx.y << 7;                                              \
    const int n0 = blockIdx.x << 7;                                              \
    const int wm = (wid & 3) * 32;                                               \
    const int wn = (wid >> 2) * 64;                                              \
    const int cr = tid >> 1;                                                     \
    const int cbase = (tid & 1) << 1;                                            \
    float acc[2][8][4];                                                          \
    _Pragma("unroll")                                                            \
    for (int a = 0; a < 2; a++)                                                  \
        _Pragma("unroll")                                                        \
        for (int n = 0; n < 8; n++)                                              \
            _Pragma("unroll")                                                    \
            for (int j = 0; j < 4; j++) acc[a][n][j] = 0.0f;                     \
    {                                                                            \
        _Pragma("unroll")                                                        \
        for (int pre = 0; pre < 2; pre++) {                                      \
            const int _k0 = pre * 32;                                            \
            const uint32_t _sbb = sb + pre * 32768u;                             \
            _Pragma("unroll")                                                    \
            for (int _j = 0; _j < 2; _j++) {                                     \
                const int _cc = cbase + _j;                                      \
                const uint32_t _so = swz(cr, _cc);                               \
                const size_t _ea = (size_t)(m0 + cr) * DMODEL + _k0 + _cc * 8;   \
                const size_t _eb = (size_t)(n0 + cr) * DMODEL + _k0 + _cc * 8;   \
                CP16(_sbb + _so,          (const void*)(Ah_ + _ea));             \
                CP16(_sbb + 8192u + _so,  (const void*)(Al_ + _ea));             \
                CP16(_sbb + 16384u + _so, (const void*)(Bh_ + _eb));             \
                CP16(_sbb + 24576u + _so, (const void*)(Bl_ + _eb));             \
            }                                                                    \
            CP_COMMIT();                                                         \
        }                                                                        \
    }                                                                            \
    _Pragma("unroll 1")                                                          \
    for (int c = 0; c < NCHUNK; c++) {                                           \
        if (c < NCHUNK - 1)                                                      \
            asm volatile("cp.async.wait_group 1;" ::: "memory");                 \
        else                                                                     \
            asm volatile("cp.async.wait_group 0;" ::: "memory");                 \
        __syncthreads();                                                         \
        const uint32_t ab = sb + (c & 1) * 32768u;                               \
        const uint32_t bbb = ab + 16384u;                                        \
        _Pragma("unroll")                                                        \
        for (int ks = 0; ks < 2; ks++) {                                         \
            uint32_t ah[2][4], al[2][4];                                         \
            _Pragma("unroll")                                                    \
            for (int a = 0; a < 2; a++) {                                        \
                const int row = wm + a * 16 + ((lane >> 3) & 1) * 8 + (lane & 7);\
                const int ch = ks * 2 + (lane >> 4);                             \
                const uint32_t off = swz(row, ch);                               \
                ldsm4(ah[a], ab + off);                                          \
                ldsm4(al[a], ab + 8192u + off);                                  \
            }                                                                    \
            _Pragma("unroll")                                                    \
            for (int g = 0; g < 4; g++) {                                        \
                const int row = wn + g * 16 + ((lane >> 4) & 1) * 8 + (lane & 7);\
                const int ch = ks * 2 + ((lane >> 3) & 1);                       \
                const uint32_t off = swz(row, ch);                               \
                uint32_t bh[4], bl[4];                                           \
                ldsm4(bh, bbb + off);                                            \
                _Pragma("unroll")                                                \
                for (int a = 0; a < 2; a++) {                                    \
                    MMA16816(acc[a][2 * g + 0], ah[a], bh + 0);                  \
                    MMA16816(acc[a][2 * g + 1], ah[a], bh + 2);                  \
                    MMA16816(acc[a][2 * g + 0], al[a], bh + 0);                  \
                    MMA16816(acc[a][2 * g + 1], al[a], bh + 2);                  \
                }                                                                \
                ldsm4(bl, bbb + 8192u + off);                                    \
                _Pragma("unroll")                                                \
                for (int a = 0; a < 2; a++) {                                    \
                    MMA16816(acc[a][2 * g + 0], ah[a], bl + 0);                  \
                    MMA16816(acc[a][2 * g + 1], ah[a], bl + 2);                  \
                }                                                                \
            }                                                                    \
        }                                                                        \
        __syncthreads();                                                         \
        if (c + 2 < NCHUNK) {                                                    \
            const int _k0 = (c + 2) * 32;                                        \
            const uint32_t _sbb = sb + (c & 1) * 32768u;                         \
            _Pragma("unroll")                                                    \
            for (int _j = 0; _j < 2; _j++) {                                     \
                const int _cc = cbase + _j;                                      \
                const uint32_t _so = swz(cr, _cc);                               \
                const size_t _ea = (size_t)(m0 + cr) * DMODEL + _k0 + _cc * 8;   \
                const size_t _eb = (size_t)(n0 + cr) * DMODEL + _k0 + _cc * 8;   \
                CP16(_sbb + _so,          (const void*)(Ah_ + _ea));             \
                CP16(_sbb + 8192u + _so,  (const void*)(Al_ + _ea));             \
                CP16(_sbb + 16384u + _so, (const void*)(Bh_ + _eb));             \
                CP16(_sbb + 24576u + _so, (const void*)(Bl_ + _eb));             \
            }                                                                    \
            CP_COMMIT();                                                         \
        }                                                                        \
    }

// ---------------------------------------------------------------------------
// Plain GEMM: fp32 C output (final projection)
// ---------------------------------------------------------------------------
__global__ void __launch_bounds__(256) gemm_mma(const __nv_bfloat16* __restrict__ Ah,
                                                const __nv_bfloat16* __restrict__ Al,
                                                const __nv_bfloat16* __restrict__ Bh,
                                                const __nv_bfloat16* __restrict__ Bl,
                                                float* __restrict__ C) {
    extern __shared__ char sm[];
    GEMM_MAINLOOP(Ah, Al, Bh, Bl)

    const int er = lane >> 2;
    const int ec = (lane & 3) * 2;
#pragma unroll
    for (int a = 0; a < 2; a++) {
#pragma unroll
        for (int n = 0; n < 8; n++) {
            float* p0 = C + (size_t)(m0 + wm + a * 16 + er) * DMODEL + n0 + wn + n * 8 + ec;
            float* p1 = p0 + 8 * DMODEL;
            *reinterpret_cast<float2*>(p0) = make_float2(acc[a][n][0], acc[a][n][1]);
            *reinterpret_cast<float2*>(p1) = make_float2(acc[a][n][2], acc[a][n][3]);
        }
    }
}

// ---------------------------------------------------------------------------
// Fused QKV GEMM: N=3072 (Q|K|V). Epilogue applies RoPE to Q,K (via table)
// and writes split bf16 outputs directly.
// ---------------------------------------------------------------------------
__global__ void __launch_bounds__(256) gemm_qkv(
    const __nv_bfloat16* __restrict__ Ah, const __nv_bfloat16* __restrict__ Al,
    const __nv_bfloat16* __restrict__ Bh, const __nv_bfloat16* __restrict__ Bl,
    const float2* __restrict__ tab,
    __nv_bfloat16* __restrict__ Qh, __nv_bfloat16* __restrict__ Ql,
    __nv_bfloat16* __restrict__ Kh, __nv_bfloat16* __restrict__ Kl,
    __nv_bfloat16* __restrict__ Vh, __nv_bfloat16* __restrict__ Vl) {
    extern __shared__ char sm[];
    GEMM_MAINLOOP(Ah, Al, Bh, Bl)

    const int er = lane >> 2;
    const int ec = (lane & 3) * 2;
    const int qkv = n0 >> 10;          // 0=Q, 1=K, 2=V
    const int ncol = n0 & 1023;        // col offset within this output

    if (qkv < 2) {
        __nv_bfloat16* Dh = (qkv == 0) ? Qh : Kh;
        __nv_bfloat16* Dl = (qkv == 0) ? Ql : Kl;
#pragma unroll
        for (int a = 0; a < 2; a++) {
#pragma unroll
            for (int nf = 0; nf < 4; nf++) {   // pair (nf, nf+4) = cols jj, jj+32
                const int jj0 = nf * 8 + ec;   // 0..30, within-head first half
                const int dcol = ncol + wn + nf * 8 + ec;
#pragma unroll
                for (int rs = 0; rs < 2; rs++) {
                    const int row = m0 + wm + a * 16 + er + rs * 8;
                    const float x1_0 = acc[a][nf][rs * 2 + 0];
                    const float x1_1 = acc[a][nf][rs * 2 + 1];
                    const float x2_0 = acc[a][nf + 4][rs * 2 + 0];
                    const float x2_1 = acc[a][nf + 4][rs * 2 + 1];
                    const float2 cs0 = tab[row * 32 + jj0];
                    const float2 cs1 = tab[row * 32 + jj0 + 1];
                    const float y1_0 = fmaf(x1_0, cs0.x, -x2_0 * cs0.y);
                    const float y2_0 = fmaf(x2_0, cs0.x,  x1_0 * cs0.y);
                    const float y1_1 = fmaf(x1_1, cs1.x, -x2_1 * cs1.y);
                    const float y2_1 = fmaf(x2_1, cs1.x,  x1_1 * cs1.y);
                    uint32_t h1, l1, h2, l2;
                    split2(y1_0, y1_1, h1, l1);
                    split2(y2_0, y2_1, h2, l2);
                    const size_t o1 = (size_t)row * DMODEL + dcol;
                    *reinterpret_cast<uint32_t*>(Dh + o1) = h1;
                    *reinterpret_cast<uint32_t*>(Dl + o1) = l1;
                    *reinterpret_cast<uint32_t*>(Dh + o1 + 32) = h2;
                    *reinterpret_cast<uint32_t*>(Dl + o1 + 32) = l2;
                }
            }
        }
    } else {
#pragma unroll
        for (int a = 0; a < 2; a++) {
#pragma unroll
            for (int nf = 0; nf < 8; nf++) {
                const int dcol = ncol + wn + nf * 8 + ec;
#pragma unroll
                for (int rs = 0; rs < 2; rs++) {
                    const int row = m0 + wm + a * 16 + er + rs * 8;
                    uint32_t h, l;
                    split2(acc[a][nf][rs * 2 + 0], acc[a][nf][rs * 2 + 1], h, l);
                    const size_t o1 = (size_t)row * DMODEL + dcol;
                    *reinterpret_cast<uint32_t*>(Vh + o1) = h;
                    *reinterpret_cast<uint32_t*>(Vl + o1) = l;
                }
            }
        }
    }
}

// ---------------------------------------------------------------------------
// RoPE table precompute
// ---------------------------------------------------------------------------
__global__ void __launch_bounds__(256) rope_table_kernel(float2* __restrict__ tab) {
    int idx = blockIdx.x * 256 + threadIdx.x;  // 131072
    int row = idx >> 5, jj = idx & 31;
    float invf = (float)pow(10000.0, -(double)jj / 32.0);
    float ang = (float)row * invf;  // fp32 product like jax
    double s, c;
    sincos((double)ang, &s, &c);
    tab[idx] = make_float2((float)c, (float)s);
}

// ---------------------------------------------------------------------------
// HMMA flash attention, 256 threads (8 warps x 16 q-rows), 128-q tile.
// Epilogue writes split bf16 O directly into Ah/Al (final GEMM input).
// smem: Qh(16K) Ql(16K) + 2 stages x (Kh,Kl,Vh,Vl 8K each) = 96KB.
// ---------------------------------------------------------------------------
#define FLASH_SMEM 98304

__global__ void __launch_bounds__(256) flash_mma(
    const __nv_bfloat16* __restrict__ Qh, const __nv_bfloat16* __restrict__ Ql,
    const __nv_bfloat16* __restrict__ Kh, const __nv_bfloat16* __restrict__ Kl,
    const __nv_bfloat16* __restrict__ Vh, const __nv_bfloat16* __restrict__ Vl,
    __nv_bfloat16* __restrict__ Oh, __nv_bfloat16* __restrict__ Ol) {
    extern __shared__ char sm[];
    const uint32_t sb = smem_u32(sm);
    const int tid = threadIdx.x;
    const int wid = tid >> 5, lane = tid & 31;
    const int qt = blockIdx.x;
    const int h = blockIdx.y;
    const bool causal = (h < NAR);
    const int wm = wid * 16;

    // ---- load Q tile (128 rows, head slice), both splits ----
    {
        const int row = tid >> 1;
        const int chb = (tid & 1) * 4;
        const size_t g = (size_t)(qt * 128 + row) * DMODEL + h * DHEAD;
#pragma unroll
        for (int j = 0; j < 4; j++) {
            const uint32_t so = swz8(row, chb + j);
            CP16(sb + so, (const void*)(Qh + g + (chb + j) * 8));
            CP16(sb + 16384u + so, (const void*)(Ql + g + (chb + j) * 8));
        }
    }
    CP_COMMIT();

    const int ktiles = causal ? (2 * qt + 2) : (LSEQ / 64);

#define ISSUEKV(kt, buf)                                                        \
    do {                                                                        \
        const int _row = tid >> 2;                                              \
        const int _cb = (tid & 3) * 2;                                          \
        const uint32_t _sbb = sb + 32768u + (buf) * 32768u;                     \
        const size_t _g = (size_t)((kt) * 64 + _row) * DMODEL + h * DHEAD;      \
        _Pragma("unroll")                                                       \
        for (int _j = 0; _j < 2; _j++) {                                        \
            const uint32_t _so = swz8(_row, _cb + _j);                          \
            const size_t _e = _g + (_cb + _j) * 8;                              \
            CP16(_sbb + _so,           (const void*)(Kh + _e));                 \
            CP16(_sbb + 8192u + _so,   (const void*)(Kl + _e));                 \
            CP16(_sbb + 16384u + _so,  (const void*)(Vh + _e));                 \
            CP16(_sbb + 24576u + _so,  (const void*)(Vl + _e));                 \
        }                                                                       \
    } while (0)

    ISSUEKV(0, 0);
    CP_COMMIT();
    ISSUEKV(1, 1);
    CP_COMMIT();

    float o[8][4];
#pragma unroll
    for (int n = 0; n < 8; n++)
#pragma unroll
        for (int j = 0; j < 4; j++) o[n][j] = 0.0f;
    float m_[2] = {-1e30f, -1e30f};
    float l_[2] = {0.0f, 0.0f};

#pragma unroll 1
    for (int kt = 0; kt < ktiles; kt++) {
        if (kt < ktiles - 1)
            asm volatile("cp.async.wait_group 1;" ::: "memory");
        else
            asm volatile("cp.async.wait_group 0;" ::: "memory");
        __syncthreads();

        const uint32_t kbase = sb + 32768u + (kt & 1) * 32768u;
        const uint32_t vbase = kbase + 16384u;

        // ---- S = Q K^T (3 split terms) ----
        float sv[8][4];
#pragma unroll
        for (int n = 0; n < 8; n++)
#pragma unroll
            for (int j = 0; j < 4; j++) sv[n][j] = 0.0f;

#pragma unroll
        for (int ks = 0; ks < 4; ks++) {
            uint32_t ah[4], al[4];
            {
                const int row = wm + ((lane >> 3) & 1) * 8 + (lane & 7);
                const int ch = ks * 2 + (lane >> 4);
                const uint32_t off = swz8(row, ch);
                ldsm4(ah, sb + off);
                ldsm4(al, sb + 16384u + off);
            }
#pragma unroll
            for (int g = 0; g < 4; g++) {
                const int krow = g * 16 + ((lane >> 4) & 1) * 8 + (lane & 7);
                const int kch = ks * 2 + ((lane >> 3) & 1);
                const uint32_t off = swz8(krow, kch);
                uint32_t kh[4], kl[4];
                ldsm4(kh, kbase + off);
                MMA16816(sv[2 * g + 0], ah, kh + 0);
                MMA16816(sv[2 * g + 1], ah, kh + 2);
                MMA16816(sv[2 * g + 0], al, kh + 0);
                MMA16816(sv[2 * g + 1], al, kh + 2);
                ldsm4(kl, kbase + 8192u + off);
                MMA16816(sv[2 * g + 0], ah, kl + 0);
                MMA16816(sv[2 * g + 1], ah, kl + 2);
            }
        }

        // ---- scale + causal mask ----
#pragma unroll
        for (int nf = 0; nf < 8; nf++)
#pragma unroll
            for (int j = 0; j < 4; j++) sv[nf][j] *= 0.125f;

        if (causal && kt >= 2 * qt) {
#pragma unroll
            for (int half = 0; half < 2; half++) {
                const int qg = qt * 128 + wm + (lane >> 2) + half * 8;
#pragma unroll
                for (int nf = 0; nf < 8; nf++) {
#pragma unroll
                    for (int j = 0; j < 2; j++) {
                        const int kv = kt * 64 + nf * 8 + (lane & 3) * 2 + j;
                        if (kv > qg) sv[nf][half * 2 + j] = -1e30f;
                    }
                }
            }
        }

        // ---- online softmax (2 rows per thread) ----
        float mnew[2];
#pragma unroll
        for (int half = 0; half < 2; half++) {
            float mx = -1e30f;
#pragma unroll
            for (int nf = 0; nf < 8; nf++)
                mx = fmaxf(mx, fmaxf(sv[nf][half * 2], sv[nf][half * 2 + 1]));
            mnew[half] = mx;
        }
#pragma unroll
        for (int r = 0; r < 2; r++) {
            mnew[r] = fmaxf(mnew[r], __shfl_xor_sync(0xffffffffu, mnew[r], 1));
            mnew[r] = fmaxf(mnew[r], __shfl_xor_sync(0xffffffffu, mnew[r], 2));
        }

        float alpha[2];
#pragma unroll
        for (int r = 0; r < 2; r++) {
            float mt = fmaxf(m_[r], mnew[r]);
            alpha[r] = __expf(m_[r] - mt);
            m_[r] = mt;
        }

        float rsum[2] = {0.0f, 0.0f};
#pragma unroll
        for (int nf = 0; nf < 8; nf++) {
#pragma unroll
            for (int half = 0; half < 2; half++) {
#pragma unroll
                for (int j = 0; j < 2; j++) {
                    float p = __expf(sv[nf][half * 2 + j] - m_[half]);
                    sv[nf][half * 2 + j] = p;
                    rsum[half] += p;
                }
            }
        }
#pragma unroll
        for (int r = 0; r < 2; r++) {
            rsum[r] += __shfl_xor_sync(0xffffffffu, rsum[r], 1);
            rsum[r] += __shfl_xor_sync(0xffffffffu, rsum[r], 2);
            l_[r] = l_[r] * alpha[r] + rsum[r];
        }
#pragma unroll
        for (int nf = 0; nf < 8; nf++)
#pragma unroll
            for (int half = 0; half < 2; half++) {
                o[nf][half * 2 + 0] *= alpha[half];
                o[nf][half * 2 + 1] *= alpha[half];
            }

        // ---- O += P V (3 split terms) ----
#pragma unroll
        for (int kg = 0; kg < 4; kg++) {
            uint32_t ph[4], pl[4];
#pragma unroll
            for (int q = 0; q < 2; q++) {
                const int nf = 2 * kg + q;
#pragma unroll
                for (int half = 0; half < 2; half++) {
                    float p0 = sv[nf][half * 2 + 0];
                    float p1 = sv[nf][half * 2 + 1];
                    split2(p0, p1, ph[q * 2 + half], pl[q * 2 + half]);
                }
            }
#pragma unroll
            for (int gd = 0; gd < 4; gd++) {
                const int vrow = kg * 16 + (lane & 15);
                const int vch = gd * 2 + (lane >> 4);
                const uint32_t off = swz8(vrow, vch);
                uint32_t vh[4], vl[4];
                ldsm4t(vh, vbase + off);
                MMA16816(o[2 * gd + 0], ph, vh + 0);
                MMA16816(o[2 * gd + 1], ph, vh + 2);
                MMA16816(o[2 * gd + 0], pl, vh + 0);
                MMA16816(o[2 * gd + 1], pl, vh + 2);
                ldsm4t(vl, vbase + 8192u + off);
                MMA16816(o[2 * gd + 0], ph, vl + 0);
                MMA16816(o[2 * gd + 1], ph, vl + 2);
            }
        }

        __syncthreads();
        if (kt + 2 < ktiles) {
            ISSUEKV(kt + 2, kt & 1);
            CP_COMMIT();
        }
    }
#undef ISSUEKV

    // ---- epilogue: normalize and store split bf16 O (into Ah/Al) ----
    const float inva = 1.0f / l_[0];
    const float invb = 1.0f / l_[1];
    const int rowa = qt * 128 + wm + (lane >> 2);
#pragma unroll
    for (int nf = 0; nf < 8; nf++) {
        const int col = h * DHEAD + nf * 8 + (lane & 3) * 2;
        uint32_t hA, lA, hB, lB;
        split2(o[nf][0] * inva, o[nf][1] * inva, hA, lA);
        split2(o[nf][2] * invb, o[nf][3] * invb, hB, lB);
        const size_t oa = (size_t)rowa * DMODEL + col;
        const size_t ob = oa + 8 * DMODEL;
        *reinterpret_cast<uint32_t*>(Oh + oa) = hA;
        *reinterpret_cast<uint32_t*>(Ol + oa) = lA;
        *reinterpret_cast<uint32_t*>(Oh + ob) = hB;
        *reinterpret_cast<uint32_t*>(Ol + ob) = lB;
    }
}

// ---------------------------------------------------------------------------
// Launch
// ---------------------------------------------------------------------------
extern "C" void kernel_launch(void* const* d_in, const int* in_sizes, int n_in,
                              void* d_out, int out_size) {
    const float* X  = (const float*)d_in[0];
    const float* Wq = (const float*)d_in[1];
    const float* Wk = (const float*)d_in[2];
    const float* Wv = (const float*)d_in[3];
    const float* Wo = (const float*)d_in[4];
    float* out = (float*)d_out;

    float2* ropep;
    __nv_bfloat16 *Ahp, *Alp, *Bthp, *Btlp;
    __nv_bfloat16 *Qhp, *Qlp, *Khp, *Klp, *Vhp, *Vlp;
    cudaGetSymbolAddress((void**)&ropep, g_rope);
    cudaGetSymbolAddress((void**)&Ahp, g_Ah);
    cudaGetSymbolAddress((void**)&Alp, g_Al);
    cudaGetSymbolAddress((void**)&Bthp, g_Bth);
    cudaGetSymbolAddress((void**)&Btlp, g_Btl);
    cudaGetSymbolAddress((void**)&Qhp, g_Qh);
    cudaGetSymbolAddress((void**)&Qlp, g_Ql);
    cudaGetSymbolAddress((void**)&Khp, g_Kh);
    cudaGetSymbolAddress((void**)&Klp, g_Kl);
    cudaGetSymbolAddress((void**)&Vhp, g_Vh);
    cudaGetSymbolAddress((void**)&Vlp, g_Vl);

    cudaFuncSetAttribute(gemm_mma, cudaFuncAttributeMaxDynamicSharedMemorySize,
                         GEMM_SMEM);
    cudaFuncSetAttribute(gemm_qkv, cudaFuncAttributeMaxDynamicSharedMemorySize,
                         GEMM_SMEM);
    cudaFuncSetAttribute(flash_mma, cudaFuncAttributeMaxDynamicSharedMemorySize,
                         FLASH_SMEM);

    dim3 wt_grid(DMODEL / 32, DMODEL / 32);    // (32, 32)
    const int splitA_blocks = (LSEQ * DMODEL / 4) / 256;  // 4096

    split_kernel<<<splitA_blocks, 256>>>(X, Ahp, Alp);
    rope_table_kernel<<<512, 256>>>(ropep);

    // Transposed splits of Wq|Wk|Wv into one [3072,1024] buffer
    wsplit_t_kernel<<<wt_grid, 256>>>(Wq, Bthp, Btlp);
    wsplit_t_kernel<<<wt_grid, 256>>>(Wk, Bthp + DMODEL * DMODEL,
                                      Btlp + DMODEL * DMODEL);
    wsplit_t_kernel<<<wt_grid, 256>>>(Wv, Bthp + 2 * DMODEL * DMODEL,
                                      Btlp + 2 * DMODEL * DMODEL);

    // Fused QKV GEMM with rope+split epilogue
    dim3 qkv_grid(3 * DMODEL / 128, LSEQ / 128);  // (24, 32)
    gemm_qkv<<<qkv_grid, 256, GEMM_SMEM>>>(Ahp, Alp, Bthp, Btlp, ropep,
                                           Qhp, Qlp, Khp, Klp, Vhp, Vlp);

    // Flash attention; writes split O into Ah/Al
    dim3 attn_grid(LSEQ / 128, NHEAD);  // (32, 16)
    flash_mma<<<attn_grid, 256, FLASH_SMEM>>>(Qhp, Qlp, Khp, Klp, Vhp, Vlp,
                                              Ahp, Alp);

    // Final projection
    wsplit_t_kernel<<<wt_grid, 256>>>(Wo, Bthp, Btlp);
    dim3 gemm_grid(DMODEL / 128, LSEQ / 128);  // (8, 32)
    gemm_mma<<<gemm_grid, 256, GEMM_SMEM>>>(Ahp, Alp, Bthp, Btlp, out);
}

// round 7
// speedup vs baseline: 3.8457x; 1.0991x over previous
#include <cuda_runtime.h>
#include <cuda_bf16.h>
#include <math.h>
#include <stdint.h>

// Problem constants
#define LSEQ 4096
#define DMODEL 1024
#define NHEAD 16
#define NAR 8
#define DHEAD 64
#define NCHUNK (DMODEL / 32)   // 32 K-chunks of 32 for GEMM

// ---------------------------------------------------------------------------
// Scratch (__device__ globals; no allocation allowed)
// ---------------------------------------------------------------------------
__device__ __nv_bfloat16 g_Ah[LSEQ * DMODEL];      // split of A operand (X, then O)
__device__ __nv_bfloat16 g_Al[LSEQ * DMODEL];
__device__ __nv_bfloat16 g_Bth[3 * DMODEL * DMODEL]; // transposed split weights [N,K]
__device__ __nv_bfloat16 g_Btl[3 * DMODEL * DMODEL];
__device__ __nv_bfloat16 g_Qh[LSEQ * DMODEL];
__device__ __nv_bfloat16 g_Ql[LSEQ * DMODEL];
__device__ __nv_bfloat16 g_Kh[LSEQ * DMODEL];
__device__ __nv_bfloat16 g_Kl[LSEQ * DMODEL];
__device__ __nv_bfloat16 g_Vh[LSEQ * DMODEL];
__device__ __nv_bfloat16 g_Vl[LSEQ * DMODEL];
__device__ float2 g_rope[LSEQ * 32];               // cos/sin table

// ---------------------------------------------------------------------------
// PTX helpers (base sm_103-safe: mma.sync / ldmatrix / cp.async only)
// ---------------------------------------------------------------------------
__device__ __forceinline__ uint32_t smem_u32(const void* p) {
    uint32_t a;
    asm("{ .reg .u64 t; cvta.to.shared.u64 t, %1; cvt.u32.u64 %0, t; }"
        : "=r"(a) : "l"(p));
    return a;
}

#define CP16(dst, src) \
    asm volatile("cp.async.cg.shared.global [%0], [%1], 16;" \
                 :: "r"(dst), "l"(src) : "memory")
#define CP_COMMIT() asm volatile("cp.async.commit_group;" ::: "memory")

__device__ __forceinline__ void ldsm4(uint32_t* r, uint32_t addr) {
    asm volatile("ldmatrix.sync.aligned.m8n8.x4.shared.b16 {%0,%1,%2,%3}, [%4];"
                 : "=r"(r[0]), "=r"(r[1]), "=r"(r[2]), "=r"(r[3]) : "r"(addr));
}
__device__ __forceinline__ void ldsm4t(uint32_t* r, uint32_t addr) {
    asm volatile("ldmatrix.sync.aligned.m8n8.x4.trans.shared.b16 {%0,%1,%2,%3}, [%4];"
                 : "=r"(r[0]), "=r"(r[1]), "=r"(r[2]), "=r"(r[3]) : "r"(addr));
}

#define MMA16816(d, a, b)                                                       \
    asm volatile(                                                               \
        "mma.sync.aligned.m16n8k16.row.col.f32.bf16.bf16.f32 "                  \
        "{%0,%1,%2,%3}, {%4,%5,%6,%7}, {%8,%9}, {%0,%1,%2,%3};"                 \
        : "+f"((d)[0]), "+f"((d)[1]), "+f"((d)[2]), "+f"((d)[3])                \
        : "r"((a)[0]), "r"((a)[1]), "r"((a)[2]), "r"((a)[3]),                   \
          "r"((b)[0]), "r"((b)[1]))

// GEMM swizzle: rows of 32 bf16 (64B), 4 chunks of 16B
__device__ __forceinline__ uint32_t swz(int row, int chunk) {
    return (uint32_t)(row * 64 + ((chunk ^ ((row >> 1) & 3)) << 4));
}
// Flash swizzle: rows of 64 bf16 (128B), 8 chunks of 16B
__device__ __forceinline__ uint32_t swz8(int row, int chunk) {
    return (uint32_t)(row * 128 + ((chunk ^ (row & 7)) << 4));
}

__device__ __forceinline__ uint32_t pack_bf16x2(float lo, float hi) {
    uint32_t d;
    asm("cvt.rn.bf16x2.f32 %0, %1, %2;" : "=r"(d) : "f"(hi), "f"(lo));
    return d;
}

// Split one fp32 pair to hi/lo bf16x2
__device__ __forceinline__ void split2(float x0, float x1,
                                       uint32_t& h, uint32_t& l) {
    __nv_bfloat16 h0 = __float2bfloat16(x0);
    __nv_bfloat16 h1 = __float2bfloat16(x1);
    __nv_bfloat162 hp(h0, h1);
    h = *reinterpret_cast<uint32_t*>(&hp);
    l = pack_bf16x2(x0 - __bfloat162float(h0), x1 - __bfloat162float(h1));
}

// ---------------------------------------------------------------------------
// Split kernel: fp32 -> (bf16 hi, bf16 lo)  (used for X only)
// ---------------------------------------------------------------------------
__global__ void __launch_bounds__(256) split_kernel(const float* __restrict__ src,
                                                    __nv_bfloat16* __restrict__ hi,
                                                    __nv_bfloat16* __restrict__ lo) {
    int idx = blockIdx.x * 256 + threadIdx.x;  // over float4s
    float4 v = reinterpret_cast<const float4*>(src)[idx];
    float x[4] = {v.x, v.y, v.z, v.w};
    __nv_bfloat16 h[4], l[4];
#pragma unroll
    for (int i = 0; i < 4; i++) {
        h[i] = __float2bfloat16(x[i]);
        l[i] = __float2bfloat16(x[i] - __bfloat162float(h[i]));
    }
    reinterpret_cast<__nv_bfloat162*>(hi)[idx * 2 + 0] = __nv_bfloat162(h[0], h[1]);
    reinterpret_cast<__nv_bfloat162*>(hi)[idx * 2 + 1] = __nv_bfloat162(h[2], h[3]);
    reinterpret_cast<__nv_bfloat162*>(lo)[idx * 2 + 0] = __nv_bfloat162(l[0], l[1]);
    reinterpret_cast<__nv_bfloat162*>(lo)[idx * 2 + 1] = __nv_bfloat162(l[2], l[3]);
}

// ---------------------------------------------------------------------------
// Transpose+split: W[K,N] fp32 -> Bt_hi/Bt_lo [N,K] bf16
// ---------------------------------------------------------------------------
__global__ void __launch_bounds__(256) wsplit_t_kernel(const float* __restrict__ W,
                                                       __nv_bfloat16* __restrict__ bth,
                                                       __nv_bfloat16* __restrict__ btl) {
    __shared__ float s[32][33];
    int tx = threadIdx.x & 31, ty = threadIdx.x >> 5;
    int n0 = blockIdx.x * 32, k0 = blockIdx.y * 32;
#pragma unroll
    for (int j = 0; j < 4; j++)
        s[ty + j * 8][tx] = W[(k0 + ty + j * 8) * DMODEL + n0 + tx];
    __syncthreads();
#pragma unroll
    for (int j = 0; j < 4; j++) {
        float x = s[tx][ty + j * 8];
        __nv_bfloat16 h = __float2bfloat16(x);
        __nv_bfloat16 l = __float2bfloat16(x - __bfloat162float(h));
        int o = (n0 + ty + j * 8) * DMODEL + k0 + tx;
        bth[o] = h;
        btl[o] = l;
    }
}

// ---------------------------------------------------------------------------
// Shared GEMM mainloop: 3-stage cp.async pipeline, 128x128 tile into acc.
// ---------------------------------------------------------------------------
#define GEMM_SMEM 98304

#define GEMM_ISSUE(Ah_, Al_, Bh_, Bl_, chunk, buf)                               \
    do {                                                                         \
        const int _k0 = (chunk) * 32;                                            \
        const uint32_t _sbb = sb + (buf) * 32768u;                               \
        _Pragma("unroll")                                                        \
        for (int _j = 0; _j < 2; _j++) {                                         \
            const int _cc = cbase + _j;                                          \
            const uint32_t _so = swz(cr, _cc);                                   \
            const size_t _ea = (size_t)(m0 + cr) * DMODEL + _k0 + _cc * 8;       \
            const size_t _eb = (size_t)(n0 + cr) * DMODEL + _k0 + _cc * 8;       \
            CP16(_sbb + _so,          (const void*)(Ah_ + _ea));                 \
            CP16(_sbb + 8192u + _so,  (const void*)(Al_ + _ea));                 \
            CP16(_sbb + 16384u + _so, (const void*)(Bh_ + _eb));                 \
            CP16(_sbb + 24576u + _so, (const void*)(Bl_ + _eb));                 \
        }                                                                        \
        CP_COMMIT();                                                             \
    } while (0)

#define GEMM_MAINLOOP(Ah_, Al_, Bh_, Bl_)                                        \
    const uint32_t sb = smem_u32(sm);                                            \
    const int tid = threadIdx.x;                                                 \
    const int wid = tid >> 5, lane = tid & 31;                                   \
    const int m0 = blockIdx.y << 7;                                              \
    const int n0 = blockIdx.x << 7;                                              \
    const int wm = (wid & 3) * 32;                                               \
    const int wn = (wid >> 2) * 64;                                              \
    const int cr = tid >> 1;                                                     \
    const int cbase = (tid & 1) << 1;                                            \
    float acc[2][8][4];                                                          \
    _Pragma("unroll")                                                            \
    for (int a = 0; a < 2; a++)                                                  \
        _Pragma("unroll")                                                        \
        for (int n = 0; n < 8; n++)                                              \
            _Pragma("unroll")                                                    \
            for (int j = 0; j < 4; j++) acc[a][n][j] = 0.0f;                     \
    GEMM_ISSUE(Ah_, Al_, Bh_, Bl_, 0, 0);                                        \
    GEMM_ISSUE(Ah_, Al_, Bh_, Bl_, 1, 1);                                        \
    GEMM_ISSUE(Ah_, Al_, Bh_, Bl_, 2, 2);                                        \
    int stage = 0;                                                               \
    _Pragma("unroll 1")                                                          \
    for (int c = 0; c < NCHUNK; c++) {                                           \
        const int rem = NCHUNK - 1 - c;                                          \
        if (rem >= 2)                                                            \
            asm volatile("cp.async.wait_group 2;" ::: "memory");                 \
        else if (rem == 1)                                                       \
            asm volatile("cp.async.wait_group 1;" ::: "memory");                 \
        else                                                                     \
            asm volatile("cp.async.wait_group 0;" ::: "memory");                 \
        __syncthreads();                                                         \
        const uint32_t ab = sb + stage * 32768u;                                 \
        const uint32_t bbb = ab + 16384u;                                        \
        _Pragma("unroll")                                                        \
        for (int ks = 0; ks < 2; ks++) {                                         \
            uint32_t ah[2][4], al[2][4];                                         \
            _Pragma("unroll")                                                    \
            for (int a = 0; a < 2; a++) {                                        \
                const int row = wm + a * 16 + ((lane >> 3) & 1) * 8 + (lane & 7);\
                const int ch = ks * 2 + (lane >> 4);                             \
                const uint32_t off = swz(row, ch);                               \
                ldsm4(ah[a], ab + off);                                          \
                ldsm4(al[a], ab + 8192u + off);                                  \
            }                                                                    \
            _Pragma("unroll")                                                    \
            for (int g = 0; g < 4; g++) {                                        \
                const int row = wn + g * 16 + ((lane >> 4) & 1) * 8 + (lane & 7);\
                const int ch = ks * 2 + ((lane >> 3) & 1);                       \
                const uint32_t off = swz(row, ch);                               \
                uint32_t bh[4], bl[4];                                           \
                ldsm4(bh, bbb + off);                                            \
                _Pragma("unroll")                                                \
                for (int a = 0; a < 2; a++) {                                    \
                    MMA16816(acc[a][2 * g + 0], ah[a], bh + 0);                  \
                    MMA16816(acc[a][2 * g + 1], ah[a], bh + 2);                  \
                    MMA16816(acc[a][2 * g + 0], al[a], bh + 0);                  \
                    MMA16816(acc[a][2 * g + 1], al[a], bh + 2);                  \
                }                                                                \
                ldsm4(bl, bbb + 8192u + off);                                    \
                _Pragma("unroll")                                                \
                for (int a = 0; a < 2; a++) {                                    \
                    MMA16816(acc[a][2 * g + 0], ah[a], bl + 0);                  \
                    MMA16816(acc[a][2 * g + 1], ah[a], bl + 2);                  \
                }                                                                \
            }                                                                    \
        }                                                                        \
        __syncthreads();                                                         \
        if (c + 3 < NCHUNK) {                                                    \
            GEMM_ISSUE(Ah_, Al_, Bh_, Bl_, c + 3, stage);                        \
        }                                                                        \
        stage = (stage == 2) ? 0 : stage + 1;                                    \
    }

// ---------------------------------------------------------------------------
// Plain GEMM: fp32 C output (final projection)
// ---------------------------------------------------------------------------
__global__ void __launch_bounds__(256) gemm_mma(const __nv_bfloat16* __restrict__ Ah,
                                                const __nv_bfloat16* __restrict__ Al,
                                                const __nv_bfloat16* __restrict__ Bh,
                                                const __nv_bfloat16* __restrict__ Bl,
                                                float* __restrict__ C) {
    extern __shared__ char sm[];
    GEMM_MAINLOOP(Ah, Al, Bh, Bl)

    const int er = lane >> 2;
    const int ec = (lane & 3) * 2;
#pragma unroll
    for (int a = 0; a < 2; a++) {
#pragma unroll
        for (int n = 0; n < 8; n++) {
            float* p0 = C + (size_t)(m0 + wm + a * 16 + er) * DMODEL + n0 + wn + n * 8 + ec;
            float* p1 = p0 + 8 * DMODEL;
            *reinterpret_cast<float2*>(p0) = make_float2(acc[a][n][0], acc[a][n][1]);
            *reinterpret_cast<float2*>(p1) = make_float2(acc[a][n][2], acc[a][n][3]);
        }
    }
}

// ---------------------------------------------------------------------------
// Fused QKV GEMM: N=3072 (Q|K|V). Epilogue applies RoPE to Q,K and writes
// split bf16 outputs directly.
// ---------------------------------------------------------------------------
__global__ void __launch_bounds__(256) gemm_qkv(
    const __nv_bfloat16* __restrict__ Ah, const __nv_bfloat16* __restrict__ Al,
    const __nv_bfloat16* __restrict__ Bh, const __nv_bfloat16* __restrict__ Bl,
    const float2* __restrict__ tab,
    __nv_bfloat16* __restrict__ Qh, __nv_bfloat16* __restrict__ Ql,
    __nv_bfloat16* __restrict__ Kh, __nv_bfloat16* __restrict__ Kl,
    __nv_bfloat16* __restrict__ Vh, __nv_bfloat16* __restrict__ Vl) {
    extern __shared__ char sm[];
    GEMM_MAINLOOP(Ah, Al, Bh, Bl)

    const int er = lane >> 2;
    const int ec = (lane & 3) * 2;
    const int qkv = n0 >> 10;          // 0=Q, 1=K, 2=V
    const int ncol = n0 & 1023;        // col offset within this output

    if (qkv < 2) {
        __nv_bfloat16* Dh = (qkv == 0) ? Qh : Kh;
        __nv_bfloat16* Dl = (qkv == 0) ? Ql : Kl;
#pragma unroll
        for (int a = 0; a < 2; a++) {
#pragma unroll
            for (int nf = 0; nf < 4; nf++) {   // pair (nf, nf+4) = cols jj, jj+32
                const int jj0 = nf * 8 + ec;   // 0..30, within-head first half
                const int dcol = ncol + wn + nf * 8 + ec;
#pragma unroll
                for (int rs = 0; rs < 2; rs++) {
                    const int row = m0 + wm + a * 16 + er + rs * 8;
                    const float x1_0 = acc[a][nf][rs * 2 + 0];
                    const float x1_1 = acc[a][nf][rs * 2 + 1];
                    const float x2_0 = acc[a][nf + 4][rs * 2 + 0];
                    const float x2_1 = acc[a][nf + 4][rs * 2 + 1];
                    const float2 cs0 = tab[row * 32 + jj0];
                    const float2 cs1 = tab[row * 32 + jj0 + 1];
                    const float y1_0 = fmaf(x1_0, cs0.x, -x2_0 * cs0.y);
                    const float y2_0 = fmaf(x2_0, cs0.x,  x1_0 * cs0.y);
                    const float y1_1 = fmaf(x1_1, cs1.x, -x2_1 * cs1.y);
                    const float y2_1 = fmaf(x2_1, cs1.x,  x1_1 * cs1.y);
                    uint32_t h1, l1, h2, l2;
                    split2(y1_0, y1_1, h1, l1);
                    split2(y2_0, y2_1, h2, l2);
                    const size_t o1 = (size_t)row * DMODEL + dcol;
                    *reinterpret_cast<uint32_t*>(Dh + o1) = h1;
                    *reinterpret_cast<uint32_t*>(Dl + o1) = l1;
                    *reinterpret_cast<uint32_t*>(Dh + o1 + 32) = h2;
                    *reinterpret_cast<uint32_t*>(Dl + o1 + 32) = l2;
                }
            }
        }
    } else {
#pragma unroll
        for (int a = 0; a < 2; a++) {
#pragma unroll
            for (int nf = 0; nf < 8; nf++) {
                const int dcol = ncol + wn + nf * 8 + ec;
#pragma unroll
                for (int rs = 0; rs < 2; rs++) {
                    const int row = m0 + wm + a * 16 + er + rs * 8;
                    uint32_t h, l;
                    split2(acc[a][nf][rs * 2 + 0], acc[a][nf][rs * 2 + 1], h, l);
                    const size_t o1 = (size_t)row * DMODEL + dcol;
                    *reinterpret_cast<uint32_t*>(Vh + o1) = h;
                    *reinterpret_cast<uint32_t*>(Vl + o1) = l;
                }
            }
        }
    }
}

// ---------------------------------------------------------------------------
// RoPE table precompute
// ---------------------------------------------------------------------------
__global__ void __launch_bounds__(256) rope_table_kernel(float2* __restrict__ tab) {
    int idx = blockIdx.x * 256 + threadIdx.x;  // 131072
    int row = idx >> 5, jj = idx & 31;
    float invf = (float)pow(10000.0, -(double)jj / 32.0);
    float ang = (float)row * invf;  // fp32 product like jax
    double s, c;
    sincos((double)ang, &s, &c);
    tab[idx] = make_float2((float)c, (float)s);
}

// ---------------------------------------------------------------------------
// HMMA flash attention, 256 threads (8 warps x 16 q-rows), 128-q tile.
// __launch_bounds__(256,2): cap regs at 128 so 2 CTAs/SM co-reside (192KB smem)
// -> one CTA's MMA phase overlaps the other's softmax phase.
// Work-ordered 1D grid: full heads first, then causal by descending qt.
// ---------------------------------------------------------------------------
#define FLASH_SMEM 98304

__global__ void __launch_bounds__(256, 2) flash_mma(
    const __nv_bfloat16* __restrict__ Qh, const __nv_bfloat16* __restrict__ Ql,
    const __nv_bfloat16* __restrict__ Kh, const __nv_bfloat16* __restrict__ Kl,
    const __nv_bfloat16* __restrict__ Vh, const __nv_bfloat16* __restrict__ Vl,
    __nv_bfloat16* __restrict__ Oh, __nv_bfloat16* __restrict__ Ol) {
    extern __shared__ char sm[];
    const uint32_t sb = smem_u32(sm);
    const int tid = threadIdx.x;
    const int wid = tid >> 5, lane = tid & 31;

    // Work-ordered schedule: heavy CTAs dispatch first.
    const int bid = blockIdx.x;
    int h, qt;
    if (bid < 256) {           // full-attention heads: 64 kv tiles each
        h = 8 + (bid & 7);
        qt = bid >> 3;
    } else {                   // causal heads: descending qt (descending work)
        const int cid = bid - 256;
        qt = 31 - (cid >> 3);
        h = cid & 7;
    }
    const bool causal = (h < NAR);
    const int wm = wid * 16;

    // ---- load Q tile (128 rows, head slice), both splits ----
    {
        const int row = tid >> 1;
        const int chb = (tid & 1) * 4;
        const size_t g = (size_t)(qt * 128 + row) * DMODEL + h * DHEAD;
#pragma unroll
        for (int j = 0; j < 4; j++) {
            const uint32_t so = swz8(row, chb + j);
            CP16(sb + so, (const void*)(Qh + g + (chb + j) * 8));
            CP16(sb + 16384u + so, (const void*)(Ql + g + (chb + j) * 8));
        }
    }
    CP_COMMIT();

    const int ktiles = causal ? (2 * qt + 2) : (LSEQ / 64);

#define ISSUEKV(kt, buf)                                                        \
    do {                                                                        \
        const int _row = tid >> 2;                                              \
        const int _cb = (tid & 3) * 2;                                          \
        const uint32_t _sbb = sb + 32768u + (buf) * 32768u;                     \
        const size_t _g = (size_t)((kt) * 64 + _row) * DMODEL + h * DHEAD;      \
        _Pragma("unroll")                                                       \
        for (int _j = 0; _j < 2; _j++) {                                        \
            const uint32_t _so = swz8(_row, _cb + _j);                          \
            const size_t _e = _g + (_cb + _j) * 8;                              \
            CP16(_sbb + _so,           (const void*)(Kh + _e));                 \
            CP16(_sbb + 8192u + _so,   (const void*)(Kl + _e));                 \
            CP16(_sbb + 16384u + _so,  (const void*)(Vh + _e));                 \
            CP16(_sbb + 24576u + _so,  (const void*)(Vl + _e));                 \
        }                                                                       \
    } while (0)

    ISSUEKV(0, 0);
    CP_COMMIT();
    ISSUEKV(1, 1);
    CP_COMMIT();

    float o[8][4];
#pragma unroll
    for (int n = 0; n < 8; n++)
#pragma unroll
        for (int j = 0; j < 4; j++) o[n][j] = 0.0f;
    float m_[2] = {-1e30f, -1e30f};
    float l_[2] = {0.0f, 0.0f};

#pragma unroll 1
    for (int kt = 0; kt < ktiles; kt++) {
        if (kt < ktiles - 1)
            asm volatile("cp.async.wait_group 1;" ::: "memory");
        else
            asm volatile("cp.async.wait_group 0;" ::: "memory");
        __syncthreads();

        const uint32_t kbase = sb + 32768u + (kt & 1) * 32768u;
        const uint32_t vbase = kbase + 16384u;

        // ---- S = Q K^T (3 split terms) ----
        float sv[8][4];
#pragma unroll
        for (int n = 0; n < 8; n++)
#pragma unroll
            for (int j = 0; j < 4; j++) sv[n][j] = 0.0f;

#pragma unroll
        for (int ks = 0; ks < 4; ks++) {
            uint32_t ah[4], al[4];
            {
                const int row = wm + ((lane >> 3) & 1) * 8 + (lane & 7);
                const int ch = ks * 2 + (lane >> 4);
                const uint32_t off = swz8(row, ch);
                ldsm4(ah, sb + off);
                ldsm4(al, sb + 16384u + off);
            }
#pragma unroll
            for (int g = 0; g < 4; g++) {
                const int krow = g * 16 + ((lane >> 4) & 1) * 8 + (lane & 7);
                const int kch = ks * 2 + ((lane >> 3) & 1);
                const uint32_t off = swz8(krow, kch);
                uint32_t kh[4], kl[4];
                ldsm4(kh, kbase + off);
                MMA16816(sv[2 * g + 0], ah, kh + 0);
                MMA16816(sv[2 * g + 1], ah, kh + 2);
                MMA16816(sv[2 * g + 0], al, kh + 0);
                MMA16816(sv[2 * g + 1], al, kh + 2);
                ldsm4(kl, kbase + 8192u + off);
                MMA16816(sv[2 * g + 0], ah, kl + 0);
                MMA16816(sv[2 * g + 1], ah, kl + 2);
            }
        }

        // ---- scale + causal mask ----
#pragma unroll
        for (int nf = 0; nf < 8; nf++)
#pragma unroll
            for (int j = 0; j < 4; j++) sv[nf][j] *= 0.125f;

        if (causal && kt >= 2 * qt) {
#pragma unroll
            for (int half = 0; half < 2; half++) {
                const int qg = qt * 128 + wm + (lane >> 2) + half * 8;
#pragma unroll
                for (int nf = 0; nf < 8; nf++) {
#pragma unroll
                    for (int j = 0; j < 2; j++) {
                        const int kv = kt * 64 + nf * 8 + (lane & 3) * 2 + j;
                        if (kv > qg) sv[nf][half * 2 + j] = -1e30f;
                    }
                }
            }
        }

        // ---- online softmax (2 rows per thread) ----
        float mnew[2];
#pragma unroll
        for (int half = 0; half < 2; half++) {
            float mx = -1e30f;
#pragma unroll
            for (int nf = 0; nf < 8; nf++)
                mx = fmaxf(mx, fmaxf(sv[nf][half * 2], sv[nf][half * 2 + 1]));
            mnew[half] = mx;
        }
#pragma unroll
        for (int r = 0; r < 2; r++) {
            mnew[r] = fmaxf(mnew[r], __shfl_xor_sync(0xffffffffu, mnew[r], 1));
            mnew[r] = fmaxf(mnew[r], __shfl_xor_sync(0xffffffffu, mnew[r], 2));
        }

        float alpha[2];
#pragma unroll
        for (int r = 0; r < 2; r++) {
            float mt = fmaxf(m_[r], mnew[r]);
            alpha[r] = __expf(m_[r] - mt);
            m_[r] = mt;
        }

        float rsum[2] = {0.0f, 0.0f};
#pragma unroll
        for (int nf = 0; nf < 8; nf++) {
#pragma unroll
            for (int half = 0; half < 2; half++) {
#pragma unroll
                for (int j = 0; j < 2; j++) {
                    float p = __expf(sv[nf][half * 2 + j] - m_[half]);
                    sv[nf][half * 2 + j] = p;
                    rsum[half] += p;
                }
            }
        }
#pragma unroll
        for (int r = 0; r < 2; r++) {
            rsum[r] += __shfl_xor_sync(0xffffffffu, rsum[r], 1);
            rsum[r] += __shfl_xor_sync(0xffffffffu, rsum[r], 2);
            l_[r] = l_[r] * alpha[r] + rsum[r];
        }
#pragma unroll
        for (int nf = 0; nf < 8; nf++)
#pragma unroll
            for (int half = 0; half < 2; half++) {
                o[nf][half * 2 + 0] *= alpha[half];
                o[nf][half * 2 + 1] *= alpha[half];
            }

        // ---- O += P V (3 split terms) ----
#pragma unroll
        for (int kg = 0; kg < 4; kg++) {
            uint32_t ph[4], pl[4];
#pragma unroll
            for (int q = 0; q < 2; q++) {
                const int nf = 2 * kg + q;
#pragma unroll
                for (int half = 0; half < 2; half++) {
                    float p0 = sv[nf][half * 2 + 0];
                    float p1 = sv[nf][half * 2 + 1];
                    split2(p0, p1, ph[q * 2 + half], pl[q * 2 + half]);
                }
            }
#pragma unroll
            for (int gd = 0; gd < 4; gd++) {
                const int vrow = kg * 16 + (lane & 15);
                const int vch = gd * 2 + (lane >> 4);
                const uint32_t off = swz8(vrow, vch);
                uint32_t vh[4], vl[4];
                ldsm4t(vh, vbase + off);
                MMA16816(o[2 * gd + 0], ph, vh + 0);
                MMA16816(o[2 * gd + 1], ph, vh + 2);
                MMA16816(o[2 * gd + 0], pl, vh + 0);
                MMA16816(o[2 * gd + 1], pl, vh + 2);
                ldsm4t(vl, vbase + 8192u + off);
                MMA16816(o[2 * gd + 0], ph, vl + 0);
                MMA16816(o[2 * gd + 1], ph, vl + 2);
            }
        }

        __syncthreads();
        if (kt + 2 < ktiles) {
            ISSUEKV(kt + 2, kt & 1);
            CP_COMMIT();
        }
    }
#undef ISSUEKV

    // ---- epilogue: normalize and store split bf16 O (into Ah/Al) ----
    const float inva = 1.0f / l_[0];
    const float invb = 1.0f / l_[1];
    const int rowa = qt * 128 + wm + (lane >> 2);
#pragma unroll
    for (int nf = 0; nf < 8; nf++) {
        const int col = h * DHEAD + nf * 8 + (lane & 3) * 2;
        uint32_t hA, lA, hB, lB;
        split2(o[nf][0] * inva, o[nf][1] * inva, hA, lA);
        split2(o[nf][2] * invb, o[nf][3] * invb, hB, lB);
        const size_t oa = (size_t)rowa * DMODEL + col;
        const size_t ob = oa + 8 * DMODEL;
        *reinterpret_cast<uint32_t*>(Oh + oa) = hA;
        *reinterpret_cast<uint32_t*>(Ol + oa) = lA;
        *reinterpret_cast<uint32_t*>(Oh + ob) = hB;
        *reinterpret_cast<uint32_t*>(Ol + ob) = lB;
    }
}

// ---------------------------------------------------------------------------
// Launch
// ---------------------------------------------------------------------------
extern "C" void kernel_launch(void* const* d_in, const int* in_sizes, int n_in,
                              void* d_out, int out_size) {
    const float* X  = (const float*)d_in[0];
    const float* Wq = (const float*)d_in[1];
    const float* Wk = (const float*)d_in[2];
    const float* Wv = (const float*)d_in[3];
    const float* Wo = (const float*)d_in[4];
    float* out = (float*)d_out;

    float2* ropep;
    __nv_bfloat16 *Ahp, *Alp, *Bthp, *Btlp;
    __nv_bfloat16 *Qhp, *Qlp, *Khp, *Klp, *Vhp, *Vlp;
    cudaGetSymbolAddress((void**)&ropep, g_rope);
    cudaGetSymbolAddress((void**)&Ahp, g_Ah);
    cudaGetSymbolAddress((void**)&Alp, g_Al);
    cudaGetSymbolAddress((void**)&Bthp, g_Bth);
    cudaGetSymbolAddress((void**)&Btlp, g_Btl);
    cudaGetSymbolAddress((void**)&Qhp, g_Qh);
    cudaGetSymbolAddress((void**)&Qlp, g_Ql);
    cudaGetSymbolAddress((void**)&Khp, g_Kh);
    cudaGetSymbolAddress((void**)&Klp, g_Kl);
    cudaGetSymbolAddress((void**)&Vhp, g_Vh);
    cudaGetSymbolAddress((void**)&Vlp, g_Vl);

    cudaFuncSetAttribute(gemm_mma, cudaFuncAttributeMaxDynamicSharedMemorySize,
                         GEMM_SMEM);
    cudaFuncSetAttribute(gemm_qkv, cudaFuncAttributeMaxDynamicSharedMemorySize,
                         GEMM_SMEM);
    cudaFuncSetAttribute(flash_mma, cudaFuncAttributeMaxDynamicSharedMemorySize,
                         FLASH_SMEM);

    dim3 wt_grid(DMODEL / 32, DMODEL / 32);    // (32, 32)
    const int splitA_blocks = (LSEQ * DMODEL / 4) / 256;  // 4096

    split_kernel<<<splitA_blocks, 256>>>(X, Ahp, Alp);
    rope_table_kernel<<<512, 256>>>(ropep);

    // Transposed splits of Wq|Wk|Wv into one [3072,1024] buffer
    wsplit_t_kernel<<<wt_grid, 256>>>(Wq, Bthp, Btlp);
    wsplit_t_kernel<<<wt_grid, 256>>>(Wk, Bthp + DMODEL * DMODEL,
                                      Btlp + DMODEL * DMODEL);
    wsplit_t_kernel<<<wt_grid, 256>>>(Wv, Bthp + 2 * DMODEL * DMODEL,
                                      Btlp + 2 * DMODEL * DMODEL);

    // Fused QKV GEMM with rope+split epilogue
    dim3 qkv_grid(3 * DMODEL / 128, LSEQ / 128);  // (24, 32)
    gemm_qkv<<<qkv_grid, 256, GEMM_SMEM>>>(Ahp, Alp, Bthp, Btlp, ropep,
                                           Qhp, Qlp, Khp, Klp, Vhp, Vlp);

    // Flash attention; writes split O into Ah/Al. Work-ordered 1D grid.
    flash_mma<<<512, 256, FLASH_SMEM>>>(Qhp, Qlp, Khp, Klp, Vhp, Vlp,
                                        Ahp, Alp);

    // Final projection
    wsplit_t_kernel<<<wt_grid, 256>>>(Wo, Bthp, Btlp);
    dim3 gemm_grid(DMODEL / 128, LSEQ / 128);  // (8, 32)
    gemm_mma<<<gemm_grid, 256, GEMM_SMEM>>>(Ahp, Alp, Bthp, Btlp, out);
}